// round 1
// baseline (speedup 1.0000x reference)
#include <cuda_runtime.h>
#include <math.h>

// Problem constants
#define L_DIM 4096
#define M_DIM 1024
#define P_DIM 4096
#define HID   512
#define NH    8
#define DH    64
#define HK    (NH * M_DIM)   // 8192 flattened (h, m)
#define DHALF 256
#define EPS_LN 1e-5f

// ---------------- scratch (static device globals; no allocation) ----------------
__device__ float g_lt [L_DIM * HID];
__device__ float g_mt [M_DIM * HID];
__device__ float g_pt [P_DIM * HID];
__device__ float g_Ql [L_DIM * HID];
__device__ float g_Kl [M_DIM * HID];
__device__ float g_Vl [M_DIM * HID];
__device__ float g_Qp [P_DIM * HID];
__device__ float g_Kp [M_DIM * HID];
__device__ float g_Vp [M_DIM * HID];
__device__ float g_awl[(size_t)L_DIM * HK];   // [L, H*M]  attn weights (lncRNA)
__device__ float g_awp[(size_t)P_DIM * HK];   // [P, H*M]  attn weights (protein)
__device__ float g_ctxl[L_DIM * HID];
__device__ float g_ctxp[P_DIM * HID];
__device__ float g_Tp [HK * HID];             // awp^T @ ctx_p   [8192, 512]
__device__ float g_Tl [HK * HID];             // awl^T @ ctx_l   [8192, 512]
__device__ float g_finl[L_DIM * HID];
__device__ float g_finp[P_DIM * HID];
__device__ float g_catl[L_DIM * 2 * HID];
__device__ float g_catp[P_DIM * 2 * HID];
__device__ float g_preL[L_DIM * DHALF];
__device__ float g_preP[P_DIM * DHALF];

// ---------------- generic tiled SGEMM ----------------
// C[M,N] = alpha * op(A)[M,K] @ op(B)[K,N]  (+bias[n]) (+Cadd[m,n]) (relu)
// TA: a(m,k) = A[k*lda + m]   else A[m*lda + k]
// TB: b(k,n) = B[n*ldb + k]   else B[k*ldb + n]
// batched over blockIdx.z with strides sA/sB/sC.
// Requires: K % 16 == 0 (all call sites satisfy this), M % 128 handled by guard.
template<bool TA, bool TB, bool RELU, bool ADDC, bool BIAS>
__global__ void __launch_bounds__(256)
gemm_k(const float* __restrict__ A, int lda, long sA,
       const float* __restrict__ B, int ldb, long sB,
       float* __restrict__ C, int ldc, long sC,
       const float* __restrict__ Cadd, int ldadd,
       const float* __restrict__ bias,
       float alpha, int Md, int Nd, int Kd)
{
    __shared__ float As[16][129];
    __shared__ float Bs[16][129];

    const int z = blockIdx.z;
    A += (long)z * sA;
    B += (long)z * sB;
    C += (long)z * sC;

    const int row0 = blockIdx.y * 128;
    const int col0 = blockIdx.x * 128;
    const int tid  = threadIdx.x;
    const int tr   = tid >> 4;     // 0..15
    const int tc   = tid & 15;     // 0..15

    float acc[8][8];
#pragma unroll
    for (int i = 0; i < 8; i++)
#pragma unroll
        for (int j = 0; j < 8; j++) acc[i][j] = 0.f;

    for (int k0 = 0; k0 < Kd; k0 += 16) {
        // ---- load A tile (128 x 16) : 8 elements / thread, coalesced per mode
#pragma unroll
        for (int i = 0; i < 8; i++) {
            int idx = tid + i * 256;
            float v = 0.f;
            if (TA) {
                int m = idx & 127, k = idx >> 7;
                int gm = row0 + m;
                if (gm < Md) v = A[(long)(k0 + k) * lda + gm];
                As[k][m] = v;
            } else {
                int k = idx & 15, m = idx >> 4;
                int gm = row0 + m;
                if (gm < Md) v = A[(long)gm * lda + k0 + k];
                As[k][m] = v;
            }
        }
        // ---- load B tile (16 x 128)
#pragma unroll
        for (int i = 0; i < 8; i++) {
            int idx = tid + i * 256;
            float v = 0.f;
            if (TB) {
                int k = idx & 15, n = idx >> 4;
                int gn = col0 + n;
                if (gn < Nd) v = B[(long)gn * ldb + k0 + k];
                Bs[k][n] = v;
            } else {
                int n = idx & 127, k = idx >> 7;
                int gn = col0 + n;
                if (gn < Nd) v = B[(long)(k0 + k) * ldb + gn];
                Bs[k][n] = v;
            }
        }
        __syncthreads();

#pragma unroll
        for (int k = 0; k < 16; k++) {
            float ra[8], rb[8];
#pragma unroll
            for (int i = 0; i < 8; i++) ra[i] = As[k][tr * 8 + i];
#pragma unroll
            for (int j = 0; j < 8; j++) rb[j] = Bs[k][tc * 8 + j];
#pragma unroll
            for (int i = 0; i < 8; i++)
#pragma unroll
                for (int j = 0; j < 8; j++)
                    acc[i][j] = fmaf(ra[i], rb[j], acc[i][j]);
        }
        __syncthreads();
    }

#pragma unroll
    for (int i = 0; i < 8; i++) {
        int gm = row0 + tr * 8 + i;
        if (gm >= Md) continue;
#pragma unroll
        for (int j = 0; j < 8; j++) {
            int gn = col0 + tc * 8 + j;
            if (gn >= Nd) continue;
            float v = acc[i][j] * alpha;
            if (BIAS) v += bias[gn];
            if (ADDC) v += Cadd[(long)gm * ldadd + gn];
            if (RELU) v = fmaxf(v, 0.f);
            C[(long)gm * ldc + gn] = v;
        }
    }
}

template<bool TA, bool TB, bool RELU, bool ADDC, bool BIAS>
static inline void gemm(const float* A, int lda, long sA,
                        const float* B, int ldb, long sB,
                        float* C, int ldc, long sC,
                        const float* Cadd, int ldadd,
                        const float* bias,
                        float alpha, int Md, int Nd, int Kd, int batch)
{
    dim3 grid((Nd + 127) / 128, (Md + 127) / 128, batch);
    gemm_k<TA, TB, RELU, ADDC, BIAS><<<grid, 256>>>(
        A, lda, sA, B, ldb, sB, C, ldc, sC, Cadd, ldadd, bias, alpha, Md, Nd, Kd);
}

// ---------------- reductions ----------------
__device__ __forceinline__ float warpRedMax(float v) {
#pragma unroll
    for (int o = 16; o > 0; o >>= 1) v = fmaxf(v, __shfl_xor_sync(0xffffffffu, v, o));
    return v;
}
__device__ __forceinline__ float warpRedSum(float v) {
#pragma unroll
    for (int o = 16; o > 0; o >>= 1) v += __shfl_xor_sync(0xffffffffu, v, o);
    return v;
}
__device__ __forceinline__ float blockMax256(float v, float* red) {
    int lane = threadIdx.x & 31, w = threadIdx.x >> 5;
    v = warpRedMax(v);
    if (lane == 0) red[w] = v;
    __syncthreads();
    float r = red[0];
#pragma unroll
    for (int i = 1; i < 8; i++) r = fmaxf(r, red[i]);
    __syncthreads();
    return r;
}
__device__ __forceinline__ float blockSum256(float v, float* red) {
    int lane = threadIdx.x & 31, w = threadIdx.x >> 5;
    v = warpRedSum(v);
    if (lane == 0) red[w] = v;
    __syncthreads();
    float r = 0.f;
#pragma unroll
    for (int i = 0; i < 8; i++) r += red[i];
    __syncthreads();
    return r;
}

// ---------------- masked softmax over each (row, head) segment of length M_DIM ----------------
// S layout: [rows, HK], segment at row*HK + h*M_DIM. mask: [rows, M_DIM] int32.
__global__ void __launch_bounds__(256)
softmax_k(float* __restrict__ S, const int* __restrict__ mask)
{
    __shared__ float red[8];
    const int l = blockIdx.x, h = blockIdx.y;
    float* row = S + (size_t)l * HK + (size_t)h * M_DIM;
    const int* mrow = mask + (size_t)l * M_DIM;
    const int t = threadIdx.x;

    float v[4];
    float mx = -3.4e38f;
#pragma unroll
    for (int i = 0; i < 4; i++) {
        int m = t + i * 256;
        float s = row[m];
        s = (mrow[m] != 0) ? s : -1e9f;
        v[i] = s;
        mx = fmaxf(mx, s);
    }
    mx = blockMax256(mx, red);
    float sum = 0.f;
#pragma unroll
    for (int i = 0; i < 4; i++) {
        float e = __expf(v[i] - mx);
        v[i] = e;
        sum += e;
    }
    sum = blockSum256(sum, red);
    float inv = __frcp_rn(sum);
#pragma unroll
    for (int i = 0; i < 4; i++) row[t + i * 256] = v[i] * inv;
}

// ---------------- concat [a | b] along columns (each 512 wide -> 1024) ----------------
__global__ void __launch_bounds__(256)
cat_k(const float* __restrict__ a, const float* __restrict__ b, float* __restrict__ c, int rows)
{
    int idx = blockIdx.x * 256 + threadIdx.x;
    int total = rows * 1024;
    if (idx < total) {
        int r = idx >> 10, col = idx & 1023;
        c[idx] = (col < 512) ? a[(r << 9) + col] : b[(r << 9) + (col - 512)];
    }
}

// ---------------- layernorm over rows of 256 ----------------
__global__ void __launch_bounds__(256)
ln_k(const float* __restrict__ x, const float* __restrict__ g, const float* __restrict__ be,
     float* __restrict__ out)
{
    __shared__ float red[8];
    const int r = blockIdx.x, t = threadIdx.x;
    float v = x[r * 256 + t];
    float mean = blockSum256(v, red) * (1.f / 256.f);
    float d = v - mean;
    float var = blockSum256(d * d, red) * (1.f / 256.f);
    out[r * 256 + t] = d * rsqrtf(var + EPS_LN) * g[t] + be[t];
}

// ---------------- launch ----------------
static inline float* symp(const void* s) {
    void* p = nullptr;
    cudaGetSymbolAddress(&p, s);
    return (float*)p;
}

extern "C" void kernel_launch(void* const* d_in, const int* in_sizes, int n_in,
                              void* d_out, int out_size)
{
    (void)in_sizes; (void)n_in; (void)out_size;
    const float* Le    = (const float*)d_in[0];
    const float* Me    = (const float*)d_in[1];
    const float* Pe    = (const float*)d_in[2];
    const int*   maskL = (const int*)  d_in[3];
    const int*   maskP = (const int*)  d_in[4];
    const float *Wl  = (const float*)d_in[5],  *bl  = (const float*)d_in[6];
    const float *Wm  = (const float*)d_in[7],  *bm  = (const float*)d_in[8];
    const float *Wp  = (const float*)d_in[9],  *bp  = (const float*)d_in[10];
    const float *Wql = (const float*)d_in[11], *bql = (const float*)d_in[12];
    const float *Wkl = (const float*)d_in[13], *bkl = (const float*)d_in[14];
    const float *Wvl = (const float*)d_in[15], *bvl = (const float*)d_in[16];
    const float *Wqp = (const float*)d_in[17], *bqp = (const float*)d_in[18];
    const float *Wkp = (const float*)d_in[19], *bkp = (const float*)d_in[20];
    const float *Wvp = (const float*)d_in[21], *bvp = (const float*)d_in[22];
    const float *Wml = (const float*)d_in[23], *bml = (const float*)d_in[24];
    const float *Wmp = (const float*)d_in[25], *bmp = (const float*)d_in[26];
    const float *g1  = (const float*)d_in[27], *be1 = (const float*)d_in[28];
    const float *g2  = (const float*)d_in[29], *be2 = (const float*)d_in[30];

    float* lt   = symp(g_lt);
    float* mt   = symp(g_mt);
    float* pt   = symp(g_pt);
    float* Ql   = symp(g_Ql);
    float* Kl   = symp(g_Kl);
    float* Vl   = symp(g_Vl);
    float* Qp   = symp(g_Qp);
    float* Kp   = symp(g_Kp);
    float* Vp   = symp(g_Vp);
    float* awl  = symp(g_awl);
    float* awp  = symp(g_awp);
    float* ctxl = symp(g_ctxl);
    float* ctxp = symp(g_ctxp);
    float* Tp   = symp(g_Tp);
    float* Tl   = symp(g_Tl);
    float* finl = symp(g_finl);
    float* finp = symp(g_finp);
    float* catl = symp(g_catl);
    float* catp = symp(g_catp);
    float* preL = symp(g_preL);
    float* preP = symp(g_preP);

    const float scale = 0.125f;   // 1/sqrt(DH=64)
    const float invH  = 0.125f;   // 1/H

    // 1) input projections (NN + bias)
    gemm<false,false,false,false,true>(Le, HID, 0, Wl, HID, 0, lt, HID, 0, nullptr, 0, bl, 1.f, L_DIM, HID, HID, 1);
    gemm<false,false,false,false,true>(Me, HID, 0, Wm, HID, 0, mt, HID, 0, nullptr, 0, bm, 1.f, M_DIM, HID, HID, 1);
    gemm<false,false,false,false,true>(Pe, HID, 0, Wp, HID, 0, pt, HID, 0, nullptr, 0, bp, 1.f, P_DIM, HID, HID, 1);

    // 2) Q/K/V projections
    gemm<false,false,false,false,true>(lt, HID, 0, Wql, HID, 0, Ql, HID, 0, nullptr, 0, bql, 1.f, L_DIM, HID, HID, 1);
    gemm<false,false,false,false,true>(mt, HID, 0, Wkl, HID, 0, Kl, HID, 0, nullptr, 0, bkl, 1.f, M_DIM, HID, HID, 1);
    gemm<false,false,false,false,true>(mt, HID, 0, Wvl, HID, 0, Vl, HID, 0, nullptr, 0, bvl, 1.f, M_DIM, HID, HID, 1);
    gemm<false,false,false,false,true>(pt, HID, 0, Wqp, HID, 0, Qp, HID, 0, nullptr, 0, bqp, 1.f, P_DIM, HID, HID, 1);
    gemm<false,false,false,false,true>(mt, HID, 0, Wkp, HID, 0, Kp, HID, 0, nullptr, 0, bkp, 1.f, M_DIM, HID, HID, 1);
    gemm<false,false,false,false,true>(mt, HID, 0, Wvp, HID, 0, Vp, HID, 0, nullptr, 0, bvp, 1.f, M_DIM, HID, HID, 1);

    // 3) attention scores (batched over heads, NT, K=DH), written into aw* at [l, h*M + m]
    gemm<false,true,false,false,false>(Ql, HID, DH, Kl, HID, DH, awl, HK, M_DIM, nullptr, 0, nullptr,
                                       scale, L_DIM, M_DIM, DH, NH);
    gemm<false,true,false,false,false>(Qp, HID, DH, Kp, HID, DH, awp, HK, M_DIM, nullptr, 0, nullptr,
                                       scale, P_DIM, M_DIM, DH, NH);

    // 4) masked softmax per (row, head)
    softmax_k<<<dim3(L_DIM, NH), 256>>>(awl, maskL);
    softmax_k<<<dim3(P_DIM, NH), 256>>>(awp, maskP);

    // 5) context (batched over heads, NN, relu epilogue)
    gemm<false,false,true,false,false>(awl, HK, M_DIM, Vl, HID, DH, ctxl, HID, DH, nullptr, 0, nullptr,
                                       1.f, L_DIM, DH, M_DIM, NH);
    gemm<false,false,true,false,false>(awp, HK, M_DIM, Vp, HID, DH, ctxp, HID, DH, nullptr, 0, nullptr,
                                       1.f, P_DIM, DH, M_DIM, NH);

    // 6) reassociated mutual: fin_l = ctx_l + (1/H) * awl @ (awp^T @ ctx_p)
    //                         fin_p = ctx_p + (1/H) * awp @ (awl^T @ ctx_l)
    gemm<true,false,false,false,false>(awp, HK, 0, ctxp, HID, 0, Tp, HID, 0, nullptr, 0, nullptr,
                                       1.f, HK, HID, P_DIM, 1);
    gemm<true,false,false,false,false>(awl, HK, 0, ctxl, HID, 0, Tl, HID, 0, nullptr, 0, nullptr,
                                       1.f, HK, HID, L_DIM, 1);
    gemm<false,false,false,true,false>(awl, HK, 0, Tp, HID, 0, finl, HID, 0, ctxl, HID, nullptr,
                                       invH, L_DIM, HID, HK, 1);
    gemm<false,false,false,true,false>(awp, HK, 0, Tl, HID, 0, finp, HID, 0, ctxp, HID, nullptr,
                                       invH, P_DIM, HID, HK, 1);

    // 7) concats
    cat_k<<<(L_DIM * 1024 + 255) / 256, 256>>>(lt,   finl, catl, L_DIM);
    cat_k<<<(P_DIM * 1024 + 255) / 256, 256>>>(finp, pt,   catp, P_DIM);

    // 8) final linears
    gemm<false,false,false,false,true>(catl, 2 * HID, 0, Wml, DHALF, 0, preL, DHALF, 0, nullptr, 0, bml,
                                       1.f, L_DIM, DHALF, 2 * HID, 1);
    gemm<false,false,false,false,true>(catp, 2 * HID, 0, Wmp, DHALF, 0, preP, DHALF, 0, nullptr, 0, bmp,
                                       1.f, P_DIM, DHALF, 2 * HID, 1);

    // 9) layernorms -> output (out_l then out_p)
    float* out = (float*)d_out;
    ln_k<<<L_DIM, 256>>>(preL, g1, be1, out);
    ln_k<<<P_DIM, 256>>>(preP, g2, be2, out + (size_t)L_DIM * DHALF);
}

// round 2
// speedup vs baseline: 1.5527x; 1.5527x over previous
#include <cuda_runtime.h>
#include <cuda_bf16.h>
#include <math.h>
#include <stdint.h>

// Problem constants
#define L_DIM 4096
#define M_DIM 1024
#define P_DIM 4096
#define HID   512
#define NH    8
#define DH    64
#define HK    (NH * M_DIM)   // 8192 flattened (h, m)
#define DHALF 256
#define EPS_LN 1e-5f

// ---------------- scratch (static device globals; no allocation) ----------------
__device__ float g_lt [L_DIM * HID];
__device__ float g_mt [M_DIM * HID];
__device__ float g_pt [P_DIM * HID];
__device__ float g_Ql [L_DIM * HID];
__device__ float g_Kl [M_DIM * HID];
__device__ float g_Vl [M_DIM * HID];
__device__ float g_Qp [P_DIM * HID];
__device__ float g_Kp [M_DIM * HID];
__device__ float g_Vp [M_DIM * HID];
__device__ float g_awl[(size_t)L_DIM * HK];   // [L, H*M]
__device__ float g_awp[(size_t)P_DIM * HK];   // [P, H*M]
__device__ float g_ctxl[L_DIM * HID];
__device__ float g_ctxp[P_DIM * HID];
__device__ float g_Tp [HK * HID];             // used as TpT f32 [HID][HK]
__device__ float g_Tl [HK * HID];             // used as TlT f32 [HID][HK]
__device__ float g_finl[L_DIM * HID];
__device__ float g_finp[P_DIM * HID];
__device__ float g_catl[L_DIM * 2 * HID];
__device__ float g_catp[P_DIM * 2 * HID];
__device__ float g_preL[L_DIM * DHALF];
__device__ float g_preP[P_DIM * DHALF];

// bf16 operand buffers for tensor-core GEMMs
__device__ __nv_bfloat16 g_bawl [(size_t)L_DIM * HK];   // [L][HK]
__device__ __nv_bfloat16 g_bawlT[(size_t)HK * L_DIM];   // [HK][L]
__device__ __nv_bfloat16 g_bawp [(size_t)P_DIM * HK];   // [P][HK]
__device__ __nv_bfloat16 g_bawpT[(size_t)HK * P_DIM];   // [HK][P]
__device__ __nv_bfloat16 g_bctxlT[HID * L_DIM];         // [HID][L]
__device__ __nv_bfloat16 g_bctxpT[HID * P_DIM];         // [HID][P]
__device__ __nv_bfloat16 g_bTpT [HID * HK];             // [HID][HK]
__device__ __nv_bfloat16 g_bTlT [HID * HK];             // [HID][HK]

// ---------------- generic tiled SGEMM (fp32, used for small GEMMs) ----------------
template<bool TA, bool TB, bool RELU, bool ADDC, bool BIAS>
__global__ void __launch_bounds__(256)
gemm_k(const float* __restrict__ A, int lda, long sA,
       const float* __restrict__ B, int ldb, long sB,
       float* __restrict__ C, int ldc, long sC,
       const float* __restrict__ Cadd, int ldadd,
       const float* __restrict__ bias,
       float alpha, int Md, int Nd, int Kd)
{
    __shared__ float As[16][129];
    __shared__ float Bs[16][129];

    const int z = blockIdx.z;
    A += (long)z * sA;
    B += (long)z * sB;
    C += (long)z * sC;

    const int row0 = blockIdx.y * 128;
    const int col0 = blockIdx.x * 128;
    const int tid  = threadIdx.x;
    const int tr   = tid >> 4;
    const int tc   = tid & 15;

    float acc[8][8];
#pragma unroll
    for (int i = 0; i < 8; i++)
#pragma unroll
        for (int j = 0; j < 8; j++) acc[i][j] = 0.f;

    for (int k0 = 0; k0 < Kd; k0 += 16) {
#pragma unroll
        for (int i = 0; i < 8; i++) {
            int idx = tid + i * 256;
            float v = 0.f;
            if (TA) {
                int m = idx & 127, k = idx >> 7;
                int gm = row0 + m;
                if (gm < Md) v = A[(long)(k0 + k) * lda + gm];
                As[k][m] = v;
            } else {
                int k = idx & 15, m = idx >> 4;
                int gm = row0 + m;
                if (gm < Md) v = A[(long)gm * lda + k0 + k];
                As[k][m] = v;
            }
        }
#pragma unroll
        for (int i = 0; i < 8; i++) {
            int idx = tid + i * 256;
            float v = 0.f;
            if (TB) {
                int k = idx & 15, n = idx >> 4;
                int gn = col0 + n;
                if (gn < Nd) v = B[(long)gn * ldb + k0 + k];
                Bs[k][n] = v;
            } else {
                int n = idx & 127, k = idx >> 7;
                int gn = col0 + n;
                if (gn < Nd) v = B[(long)(k0 + k) * ldb + gn];
                Bs[k][n] = v;
            }
        }
        __syncthreads();

#pragma unroll
        for (int k = 0; k < 16; k++) {
            float ra[8], rb[8];
#pragma unroll
            for (int i = 0; i < 8; i++) ra[i] = As[k][tr * 8 + i];
#pragma unroll
            for (int j = 0; j < 8; j++) rb[j] = Bs[k][tc * 8 + j];
#pragma unroll
            for (int i = 0; i < 8; i++)
#pragma unroll
                for (int j = 0; j < 8; j++)
                    acc[i][j] = fmaf(ra[i], rb[j], acc[i][j]);
        }
        __syncthreads();
    }

#pragma unroll
    for (int i = 0; i < 8; i++) {
        int gm = row0 + tr * 8 + i;
        if (gm >= Md) continue;
#pragma unroll
        for (int j = 0; j < 8; j++) {
            int gn = col0 + tc * 8 + j;
            if (gn >= Nd) continue;
            float v = acc[i][j] * alpha;
            if (BIAS) v += bias[gn];
            if (ADDC) v += Cadd[(long)gm * ldadd + gn];
            if (RELU) v = fmaxf(v, 0.f);
            C[(long)gm * ldc + gn] = v;
        }
    }
}

template<bool TA, bool TB, bool RELU, bool ADDC, bool BIAS>
static inline void gemm(const float* A, int lda, long sA,
                        const float* B, int ldb, long sB,
                        float* C, int ldc, long sC,
                        const float* Cadd, int ldadd,
                        const float* bias,
                        float alpha, int Md, int Nd, int Kd, int batch)
{
    dim3 grid((Nd + 127) / 128, (Md + 127) / 128, batch);
    gemm_k<TA, TB, RELU, ADDC, BIAS><<<grid, 256>>>(
        A, lda, sA, B, ldb, sB, C, ldc, sC, Cadd, ldadd, bias, alpha, Md, Nd, Kd);
}

// ---------------- bf16 tensor-core GEMM ----------------
// C[M,N](f32) = alpha * A[M,K](bf16, row-major) @ B[N,K](bf16, row-major)^T (+ Cadd)
// Requires M%128==0, N%128==0, K%32==0.
#define BMM 128
#define BNN 128
#define BKK 32
#define BKP 40   // padded halves per smem row (80B stride -> conflict-free)

__device__ __forceinline__ uint32_t smem_u32(const void* p) {
    return (uint32_t)__cvta_generic_to_shared(p);
}

template<bool ADDC>
__global__ void __launch_bounds__(256)
bf16gemm_k(const __nv_bfloat16* __restrict__ A,
           const __nv_bfloat16* __restrict__ B,
           float* __restrict__ C,
           const float* __restrict__ Cadd,
           float alpha, int Md, int Nd, int Kd)
{
    __shared__ __nv_bfloat16 sA[2][BMM * BKP];
    __shared__ __nv_bfloat16 sB[2][BNN * BKP];

    const int tid  = threadIdx.x;
    const int m0   = blockIdx.y * BMM;
    const int n0   = blockIdx.x * BNN;
    const int wid  = tid >> 5, lane = tid & 31;
    const int wr   = wid >> 1, wc = wid & 1;     // 4x2 warp grid, warp tile 32x64

    float acc[2][8][4];
#pragma unroll
    for (int mi = 0; mi < 2; mi++)
#pragma unroll
        for (int ni = 0; ni < 8; ni++)
#pragma unroll
            for (int q = 0; q < 4; q++) acc[mi][ni][q] = 0.f;

    const int KT = Kd / BKK;

    auto load_stage = [&](int s, int kt) {
#pragma unroll
        for (int i = 0; i < 2; i++) {
            int idx = tid + i * 256;            // 0..511
            int r = idx >> 2, c4 = idx & 3;
            const __nv_bfloat16* g = A + (size_t)(m0 + r) * Kd + kt * BKK + c4 * 8;
            uint32_t sa = smem_u32(&sA[s][r * BKP + c4 * 8]);
            asm volatile("cp.async.ca.shared.global [%0], [%1], 16;\n" :: "r"(sa), "l"(g));
        }
#pragma unroll
        for (int i = 0; i < 2; i++) {
            int idx = tid + i * 256;
            int r = idx >> 2, c4 = idx & 3;
            const __nv_bfloat16* g = B + (size_t)(n0 + r) * Kd + kt * BKK + c4 * 8;
            uint32_t sb = smem_u32(&sB[s][r * BKP + c4 * 8]);
            asm volatile("cp.async.ca.shared.global [%0], [%1], 16;\n" :: "r"(sb), "l"(g));
        }
        asm volatile("cp.async.commit_group;\n");
    };

    load_stage(0, 0);

    for (int kt = 0; kt < KT; kt++) {
        const int s = kt & 1;
        if (kt + 1 < KT) {
            load_stage(s ^ 1, kt + 1);
            asm volatile("cp.async.wait_group 1;\n" ::: "memory");
        } else {
            asm volatile("cp.async.wait_group 0;\n" ::: "memory");
        }
        __syncthreads();

#pragma unroll
        for (int ks = 0; ks < 2; ks++) {
            uint32_t a[2][4], b[8][2];
#pragma unroll
            for (int mi = 0; mi < 2; mi++) {
                int row = wr * 32 + mi * 16 + (lane & 15);
                int col = ks * 16 + (lane >> 4) * 8;
                uint32_t addr = smem_u32(&sA[s][row * BKP + col]);
                asm volatile("ldmatrix.sync.aligned.m8n8.x4.shared.b16 {%0,%1,%2,%3}, [%4];\n"
                             : "=r"(a[mi][0]), "=r"(a[mi][1]), "=r"(a[mi][2]), "=r"(a[mi][3])
                             : "r"(addr));
            }
#pragma unroll
            for (int j = 0; j < 4; j++) {
                int n   = wc * 64 + j * 16 + (lane & 7) + ((lane >> 4) << 3);
                int col = ks * 16 + ((lane >> 3) & 1) * 8;
                uint32_t addr = smem_u32(&sB[s][n * BKP + col]);
                uint32_t r0, r1, r2, r3;
                asm volatile("ldmatrix.sync.aligned.m8n8.x4.shared.b16 {%0,%1,%2,%3}, [%4];\n"
                             : "=r"(r0), "=r"(r1), "=r"(r2), "=r"(r3) : "r"(addr));
                b[2 * j][0] = r0; b[2 * j][1] = r1;
                b[2 * j + 1][0] = r2; b[2 * j + 1][1] = r3;
            }
#pragma unroll
            for (int mi = 0; mi < 2; mi++)
#pragma unroll
                for (int ni = 0; ni < 8; ni++)
                    asm volatile(
                        "mma.sync.aligned.m16n8k16.row.col.f32.bf16.bf16.f32 "
                        "{%0,%1,%2,%3}, {%4,%5,%6,%7}, {%8,%9}, {%0,%1,%2,%3};\n"
                        : "+f"(acc[mi][ni][0]), "+f"(acc[mi][ni][1]),
                          "+f"(acc[mi][ni][2]), "+f"(acc[mi][ni][3])
                        : "r"(a[mi][0]), "r"(a[mi][1]), "r"(a[mi][2]), "r"(a[mi][3]),
                          "r"(b[ni][0]), "r"(b[ni][1]));
        }
        __syncthreads();
    }

    // epilogue
#pragma unroll
    for (int mi = 0; mi < 2; mi++) {
        int row = m0 + wr * 32 + mi * 16 + (lane >> 2);
#pragma unroll
        for (int ni = 0; ni < 8; ni++) {
            int col = n0 + wc * 64 + ni * 8 + (lane & 3) * 2;
            float2 lo = make_float2(acc[mi][ni][0] * alpha, acc[mi][ni][1] * alpha);
            float2 hi = make_float2(acc[mi][ni][2] * alpha, acc[mi][ni][3] * alpha);
            if (ADDC) {
                float2 c0 = *(const float2*)&Cadd[(size_t)row * Nd + col];
                float2 c1 = *(const float2*)&Cadd[(size_t)(row + 8) * Nd + col];
                lo.x += c0.x; lo.y += c0.y;
                hi.x += c1.x; hi.y += c1.y;
            }
            *(float2*)&C[(size_t)row * Nd + col]       = lo;
            *(float2*)&C[(size_t)(row + 8) * Nd + col] = hi;
        }
    }
}

static inline void bf16gemm(const __nv_bfloat16* A, const __nv_bfloat16* B,
                            float* C, const float* Cadd, float alpha,
                            int Md, int Nd, int Kd)
{
    dim3 grid(Nd / BNN, Md / BMM);
    if (Cadd) bf16gemm_k<true ><<<grid, 256>>>(A, B, C, Cadd, alpha, Md, Nd, Kd);
    else      bf16gemm_k<false><<<grid, 256>>>(A, B, C, nullptr, alpha, Md, Nd, Kd);
}

// ---------------- conversions ----------------
__global__ void __launch_bounds__(256)
conv_k(const float4* __restrict__ in, __nv_bfloat162* __restrict__ out, int n4)
{
    int i = blockIdx.x * 256 + threadIdx.x;
    if (i < n4) {
        float4 v = in[i];
        out[2 * i]     = __floats2bfloat162_rn(v.x, v.y);
        out[2 * i + 1] = __floats2bfloat162_rn(v.z, v.w);
    }
}

// out[C][R] (bf16) = transpose of in[R][C] (f32). R,C multiples of 32.
__global__ void __launch_bounds__(256)
tconv_k(const float* __restrict__ in, __nv_bfloat16* __restrict__ out, int R, int C)
{
    __shared__ float t[32][33];
    int c0 = blockIdx.x * 32, r0 = blockIdx.y * 32;
    int x = threadIdx.x & 31, y = threadIdx.x >> 5;   // 32 x 8
#pragma unroll
    for (int j = 0; j < 32; j += 8)
        t[y + j][x] = in[(size_t)(r0 + y + j) * C + c0 + x];
    __syncthreads();
#pragma unroll
    for (int j = 0; j < 32; j += 8)
        out[(size_t)(c0 + y + j) * R + r0 + x] = __float2bfloat16(t[x][y + j]);
}

// ---------------- reductions ----------------
__device__ __forceinline__ float warpRedMax(float v) {
#pragma unroll
    for (int o = 16; o > 0; o >>= 1) v = fmaxf(v, __shfl_xor_sync(0xffffffffu, v, o));
    return v;
}
__device__ __forceinline__ float warpRedSum(float v) {
#pragma unroll
    for (int o = 16; o > 0; o >>= 1) v += __shfl_xor_sync(0xffffffffu, v, o);
    return v;
}
__device__ __forceinline__ float blockMax256(float v, float* red) {
    int lane = threadIdx.x & 31, w = threadIdx.x >> 5;
    v = warpRedMax(v);
    if (lane == 0) red[w] = v;
    __syncthreads();
    float r = red[0];
#pragma unroll
    for (int i = 1; i < 8; i++) r = fmaxf(r, red[i]);
    __syncthreads();
    return r;
}
__device__ __forceinline__ float blockSum256(float v, float* red) {
    int lane = threadIdx.x & 31, w = threadIdx.x >> 5;
    v = warpRedSum(v);
    if (lane == 0) red[w] = v;
    __syncthreads();
    float r = 0.f;
#pragma unroll
    for (int i = 0; i < 8; i++) r += red[i];
    __syncthreads();
    return r;
}

// ---------------- masked softmax ----------------
__global__ void __launch_bounds__(256)
softmax_k(float* __restrict__ S, const int* __restrict__ mask)
{
    __shared__ float red[8];
    const int l = blockIdx.x, h = blockIdx.y;
    float* row = S + (size_t)l * HK + (size_t)h * M_DIM;
    const int* mrow = mask + (size_t)l * M_DIM;
    const int t = threadIdx.x;

    float v[4];
    float mx = -3.4e38f;
#pragma unroll
    for (int i = 0; i < 4; i++) {
        int m = t + i * 256;
        float s = row[m];
        s = (mrow[m] != 0) ? s : -1e9f;
        v[i] = s;
        mx = fmaxf(mx, s);
    }
    mx = blockMax256(mx, red);
    float sum = 0.f;
#pragma unroll
    for (int i = 0; i < 4; i++) {
        float e = __expf(v[i] - mx);
        v[i] = e;
        sum += e;
    }
    sum = blockSum256(sum, red);
    float inv = __frcp_rn(sum);
#pragma unroll
    for (int i = 0; i < 4; i++) row[t + i * 256] = v[i] * inv;
}

// ---------------- concat ----------------
__global__ void __launch_bounds__(256)
cat_k(const float* __restrict__ a, const float* __restrict__ b, float* __restrict__ c, int rows)
{
    int idx = blockIdx.x * 256 + threadIdx.x;
    int total = rows * 1024;
    if (idx < total) {
        int r = idx >> 10, col = idx & 1023;
        c[idx] = (col < 512) ? a[(r << 9) + col] : b[(r << 9) + (col - 512)];
    }
}

// ---------------- layernorm ----------------
__global__ void __launch_bounds__(256)
ln_k(const float* __restrict__ x, const float* __restrict__ g, const float* __restrict__ be,
     float* __restrict__ out)
{
    __shared__ float red[8];
    const int r = blockIdx.x, t = threadIdx.x;
    float v = x[r * 256 + t];
    float mean = blockSum256(v, red) * (1.f / 256.f);
    float d = v - mean;
    float var = blockSum256(d * d, red) * (1.f / 256.f);
    out[r * 256 + t] = d * rsqrtf(var + EPS_LN) * g[t] + be[t];
}

// ---------------- launch ----------------
static inline void* symraw(const void* s) {
    void* p = nullptr;
    cudaGetSymbolAddress(&p, s);
    return p;
}

extern "C" void kernel_launch(void* const* d_in, const int* in_sizes, int n_in,
                              void* d_out, int out_size)
{
    (void)in_sizes; (void)n_in; (void)out_size;
    const float* Le    = (const float*)d_in[0];
    const float* Me    = (const float*)d_in[1];
    const float* Pe    = (const float*)d_in[2];
    const int*   maskL = (const int*)  d_in[3];
    const int*   maskP = (const int*)  d_in[4];
    const float *Wl  = (const float*)d_in[5],  *bl  = (const float*)d_in[6];
    const float *Wm  = (const float*)d_in[7],  *bm  = (const float*)d_in[8];
    const float *Wp  = (const float*)d_in[9],  *bp  = (const float*)d_in[10];
    const float *Wql = (const float*)d_in[11], *bql = (const float*)d_in[12];
    const float *Wkl = (const float*)d_in[13], *bkl = (const float*)d_in[14];
    const float *Wvl = (const float*)d_in[15], *bvl = (const float*)d_in[16];
    const float *Wqp = (const float*)d_in[17], *bqp = (const float*)d_in[18];
    const float *Wkp = (const float*)d_in[19], *bkp = (const float*)d_in[20];
    const float *Wvp = (const float*)d_in[21], *bvp = (const float*)d_in[22];
    const float *Wml = (const float*)d_in[23], *bml = (const float*)d_in[24];
    const float *Wmp = (const float*)d_in[25], *bmp = (const float*)d_in[26];
    const float *g1  = (const float*)d_in[27], *be1 = (const float*)d_in[28];
    const float *g2  = (const float*)d_in[29], *be2 = (const float*)d_in[30];

    float* lt   = (float*)symraw(g_lt);
    float* mt   = (float*)symraw(g_mt);
    float* pt   = (float*)symraw(g_pt);
    float* Ql   = (float*)symraw(g_Ql);
    float* Kl   = (float*)symraw(g_Kl);
    float* Vl   = (float*)symraw(g_Vl);
    float* Qp   = (float*)symraw(g_Qp);
    float* Kp   = (float*)symraw(g_Kp);
    float* Vp   = (float*)symraw(g_Vp);
    float* awl  = (float*)symraw(g_awl);
    float* awp  = (float*)symraw(g_awp);
    float* ctxl = (float*)symraw(g_ctxl);
    float* ctxp = (float*)symraw(g_ctxp);
    float* TpT  = (float*)symraw(g_Tp);
    float* TlT  = (float*)symraw(g_Tl);
    float* finl = (float*)symraw(g_finl);
    float* finp = (float*)symraw(g_finp);
    float* catl = (float*)symraw(g_catl);
    float* catp = (float*)symraw(g_catp);
    float* preL = (float*)symraw(g_preL);
    float* preP = (float*)symraw(g_preP);

    __nv_bfloat16* bawl   = (__nv_bfloat16*)symraw(g_bawl);
    __nv_bfloat16* bawlT  = (__nv_bfloat16*)symraw(g_bawlT);
    __nv_bfloat16* bawp   = (__nv_bfloat16*)symraw(g_bawp);
    __nv_bfloat16* bawpT  = (__nv_bfloat16*)symraw(g_bawpT);
    __nv_bfloat16* bctxlT = (__nv_bfloat16*)symraw(g_bctxlT);
    __nv_bfloat16* bctxpT = (__nv_bfloat16*)symraw(g_bctxpT);
    __nv_bfloat16* bTpT   = (__nv_bfloat16*)symraw(g_bTpT);
    __nv_bfloat16* bTlT   = (__nv_bfloat16*)symraw(g_bTlT);

    const float scale = 0.125f;   // 1/sqrt(DH)
    const float invH  = 0.125f;   // 1/H

    // 1) input projections
    gemm<false,false,false,false,true>(Le, HID, 0, Wl, HID, 0, lt, HID, 0, nullptr, 0, bl, 1.f, L_DIM, HID, HID, 1);
    gemm<false,false,false,false,true>(Me, HID, 0, Wm, HID, 0, mt, HID, 0, nullptr, 0, bm, 1.f, M_DIM, HID, HID, 1);
    gemm<false,false,false,false,true>(Pe, HID, 0, Wp, HID, 0, pt, HID, 0, nullptr, 0, bp, 1.f, P_DIM, HID, HID, 1);

    // 2) Q/K/V projections
    gemm<false,false,false,false,true>(lt, HID, 0, Wql, HID, 0, Ql, HID, 0, nullptr, 0, bql, 1.f, L_DIM, HID, HID, 1);
    gemm<false,false,false,false,true>(mt, HID, 0, Wkl, HID, 0, Kl, HID, 0, nullptr, 0, bkl, 1.f, M_DIM, HID, HID, 1);
    gemm<false,false,false,false,true>(mt, HID, 0, Wvl, HID, 0, Vl, HID, 0, nullptr, 0, bvl, 1.f, M_DIM, HID, HID, 1);
    gemm<false,false,false,false,true>(pt, HID, 0, Wqp, HID, 0, Qp, HID, 0, nullptr, 0, bqp, 1.f, P_DIM, HID, HID, 1);
    gemm<false,false,false,false,true>(mt, HID, 0, Wkp, HID, 0, Kp, HID, 0, nullptr, 0, bkp, 1.f, M_DIM, HID, HID, 1);
    gemm<false,false,false,false,true>(mt, HID, 0, Wvp, HID, 0, Vp, HID, 0, nullptr, 0, bvp, 1.f, M_DIM, HID, HID, 1);

    // 3) attention scores (batched over heads, NT, K=DH)
    gemm<false,true,false,false,false>(Ql, HID, DH, Kl, HID, DH, awl, HK, M_DIM, nullptr, 0, nullptr,
                                       scale, L_DIM, M_DIM, DH, NH);
    gemm<false,true,false,false,false>(Qp, HID, DH, Kp, HID, DH, awp, HK, M_DIM, nullptr, 0, nullptr,
                                       scale, P_DIM, M_DIM, DH, NH);

    // 4) masked softmax
    softmax_k<<<dim3(L_DIM, NH), 256>>>(awl, maskL);
    softmax_k<<<dim3(P_DIM, NH), 256>>>(awp, maskP);

    // 5) context (batched over heads, NN, relu)
    gemm<false,false,true,false,false>(awl, HK, M_DIM, Vl, HID, DH, ctxl, HID, DH, nullptr, 0, nullptr,
                                       1.f, L_DIM, DH, M_DIM, NH);
    gemm<false,false,true,false,false>(awp, HK, M_DIM, Vp, HID, DH, ctxp, HID, DH, nullptr, 0, nullptr,
                                       1.f, P_DIM, DH, M_DIM, NH);

    // 6) bf16 conversions for the mutual chain
    {
        int n4;
        n4 = (L_DIM * (HK / 4));
        conv_k<<<(n4 + 255) / 256, 256>>>((const float4*)awl, (__nv_bfloat162*)bawl, n4);
        n4 = (P_DIM * (HK / 4));
        conv_k<<<(n4 + 255) / 256, 256>>>((const float4*)awp, (__nv_bfloat162*)bawp, n4);
        tconv_k<<<dim3(HK / 32, L_DIM / 32), 256>>>(awl, bawlT, L_DIM, HK);
        tconv_k<<<dim3(HK / 32, P_DIM / 32), 256>>>(awp, bawpT, P_DIM, HK);
        tconv_k<<<dim3(HID / 32, L_DIM / 32), 256>>>(ctxl, bctxlT, L_DIM, HID);
        tconv_k<<<dim3(HID / 32, P_DIM / 32), 256>>>(ctxp, bctxpT, P_DIM, HID);
    }

    // 7) reassociated mutual via tensor cores:
    //    TpT[HID,HK] = ctxp^T @ awp  ;  finl = ctxl + (1/H) * awl @ TpT^T
    //    TlT[HID,HK] = ctxl^T @ awl  ;  finp = ctxp + (1/H) * awp @ TlT^T
    bf16gemm(bctxpT, bawpT, TpT, nullptr, 1.f, HID, HK, P_DIM);
    {
        int n4 = HID * (HK / 4);
        conv_k<<<(n4 + 255) / 256, 256>>>((const float4*)TpT, (__nv_bfloat162*)bTpT, n4);
    }
    bf16gemm(bawl, bTpT, finl, ctxl, invH, L_DIM, HID, HK);

    bf16gemm(bctxlT, bawlT, TlT, nullptr, 1.f, HID, HK, L_DIM);
    {
        int n4 = HID * (HK / 4);
        conv_k<<<(n4 + 255) / 256, 256>>>((const float4*)TlT, (__nv_bfloat162*)bTlT, n4);
    }
    bf16gemm(bawp, bTlT, finp, ctxp, invH, P_DIM, HID, HK);

    // 8) concats
    cat_k<<<(L_DIM * 1024 + 255) / 256, 256>>>(lt,   finl, catl, L_DIM);
    cat_k<<<(P_DIM * 1024 + 255) / 256, 256>>>(finp, pt,   catp, P_DIM);

    // 9) final linears
    gemm<false,false,false,false,true>(catl, 2 * HID, 0, Wml, DHALF, 0, preL, DHALF, 0, nullptr, 0, bml,
                                       1.f, L_DIM, DHALF, 2 * HID, 1);
    gemm<false,false,false,false,true>(catp, 2 * HID, 0, Wmp, DHALF, 0, preP, DHALF, 0, nullptr, 0, bmp,
                                       1.f, P_DIM, DHALF, 2 * HID, 1);

    // 10) layernorms -> output
    float* out = (float*)d_out;
    ln_k<<<L_DIM, 256>>>(preL, g1, be1, out);
    ln_k<<<P_DIM, 256>>>(preP, g2, be2, out + (size_t)L_DIM * DHALF);
}

// round 4
// speedup vs baseline: 1.5621x; 1.0061x over previous
#include <cuda_runtime.h>
#include <cuda_bf16.h>
#include <math.h>
#include <stdint.h>

// Problem constants
#define L_DIM 4096
#define M_DIM 1024
#define P_DIM 4096
#define HID   512
#define NH    8
#define DH    64
#define HK    (NH * M_DIM)   // 8192 flattened (h, m)
#define DHALF 256
#define EPS_LN 1e-5f

// ---------------- scratch (static device globals; no allocation) ----------------
__device__ float g_lt [L_DIM * HID];
__device__ float g_mt [M_DIM * HID];
__device__ float g_pt [P_DIM * HID];
__device__ float g_Ql [L_DIM * HID];
__device__ float g_Kl [M_DIM * HID];
__device__ float g_Vl [M_DIM * HID];
__device__ float g_Qp [P_DIM * HID];
__device__ float g_Kp [M_DIM * HID];
__device__ float g_Vp [M_DIM * HID];
__device__ float g_awl[(size_t)L_DIM * HK];   // [L, H*M]
__device__ float g_awp[(size_t)P_DIM * HK];   // [P, H*M]
__device__ float g_ctxl[L_DIM * HID];
__device__ float g_ctxp[P_DIM * HID];
__device__ float g_finl[L_DIM * HID];
__device__ float g_finp[P_DIM * HID];
__device__ float g_preL[L_DIM * DHALF];
__device__ float g_preP[P_DIM * DHALF];

// bf16 operand buffers
__device__ __nv_bfloat16 g_bawl [(size_t)L_DIM * HK];   // [L][HK]
__device__ __nv_bfloat16 g_bawlT[(size_t)HK * L_DIM];   // [HK][L]
__device__ __nv_bfloat16 g_bawp [(size_t)P_DIM * HK];   // [P][HK]
__device__ __nv_bfloat16 g_bawpT[(size_t)HK * P_DIM];   // [HK][P]
__device__ __nv_bfloat16 g_bctxlT[HID * L_DIM];         // [HID][L]
__device__ __nv_bfloat16 g_bctxpT[HID * P_DIM];         // [HID][P]
__device__ __nv_bfloat16 g_bTpT [HID * HK];             // [HID][HK] bf16 (direct GEMM output)
__device__ __nv_bfloat16 g_bTlT [HID * HK];             // [HID][HK]

// ---------------- generic tiled SGEMM (fp32 path) ----------------
template<bool TA, bool TB, bool RELU, bool ADDC, bool BIAS>
__global__ void __launch_bounds__(256)
gemm_k(const float* __restrict__ A, int lda, long sA,
       const float* __restrict__ B, int ldb, long sB,
       float* __restrict__ C, int ldc, long sC,
       const float* __restrict__ Cadd, int ldadd,
       const float* __restrict__ bias,
       float alpha, int Md, int Nd, int Kd)
{
    __shared__ float As[16][129];
    __shared__ float Bs[16][129];

    const int z = blockIdx.z;
    A += (long)z * sA;
    B += (long)z * sB;
    C += (long)z * sC;

    const int row0 = blockIdx.y * 128;
    const int col0 = blockIdx.x * 128;
    const int tid  = threadIdx.x;
    const int tr   = tid >> 4;
    const int tc   = tid & 15;

    float acc[8][8];
#pragma unroll
    for (int i = 0; i < 8; i++)
#pragma unroll
        for (int j = 0; j < 8; j++) acc[i][j] = 0.f;

    for (int k0 = 0; k0 < Kd; k0 += 16) {
#pragma unroll
        for (int i = 0; i < 8; i++) {
            int idx = tid + i * 256;
            float v = 0.f;
            if (TA) {
                int m = idx & 127, k = idx >> 7;
                int gm = row0 + m;
                if (gm < Md) v = A[(long)(k0 + k) * lda + gm];
                As[k][m] = v;
            } else {
                int k = idx & 15, m = idx >> 4;
                int gm = row0 + m;
                if (gm < Md) v = A[(long)gm * lda + k0 + k];
                As[k][m] = v;
            }
        }
#pragma unroll
        for (int i = 0; i < 8; i++) {
            int idx = tid + i * 256;
            float v = 0.f;
            if (TB) {
                int k = idx & 15, n = idx >> 4;
                int gn = col0 + n;
                if (gn < Nd) v = B[(long)gn * ldb + k0 + k];
                Bs[k][n] = v;
            } else {
                int n = idx & 127, k = idx >> 7;
                int gn = col0 + n;
                if (gn < Nd) v = B[(long)(k0 + k) * ldb + gn];
                Bs[k][n] = v;
            }
        }
        __syncthreads();

#pragma unroll
        for (int k = 0; k < 16; k++) {
            float ra[8], rb[8];
#pragma unroll
            for (int i = 0; i < 8; i++) ra[i] = As[k][tr * 8 + i];
#pragma unroll
            for (int j = 0; j < 8; j++) rb[j] = Bs[k][tc * 8 + j];
#pragma unroll
            for (int i = 0; i < 8; i++)
#pragma unroll
                for (int j = 0; j < 8; j++)
                    acc[i][j] = fmaf(ra[i], rb[j], acc[i][j]);
        }
        __syncthreads();
    }

#pragma unroll
    for (int i = 0; i < 8; i++) {
        int gm = row0 + tr * 8 + i;
        if (gm >= Md) continue;
#pragma unroll
        for (int j = 0; j < 8; j++) {
            int gn = col0 + tc * 8 + j;
            if (gn >= Nd) continue;
            float v = acc[i][j] * alpha;
            if (BIAS) v += bias[gn];
            if (ADDC) v += Cadd[(long)gm * ldadd + gn];
            if (RELU) v = fmaxf(v, 0.f);
            C[(long)gm * ldc + gn] = v;
        }
    }
}

template<bool TA, bool TB, bool RELU, bool ADDC, bool BIAS>
static inline void gemm(const float* A, int lda, long sA,
                        const float* B, int ldb, long sB,
                        float* C, int ldc, long sC,
                        const float* Cadd, int ldadd,
                        const float* bias,
                        float alpha, int Md, int Nd, int Kd, int batch)
{
    dim3 grid((Nd + 127) / 128, (Md + 127) / 128, batch);
    gemm_k<TA, TB, RELU, ADDC, BIAS><<<grid, 256>>>(
        A, lda, sA, B, ldb, sB, C, ldc, sC, Cadd, ldadd, bias, alpha, Md, Nd, Kd);
}

// ================= bf16 tensor-core GEMM (mma.sync, 3-stage pipeline) =================
// C[M,N] = alpha * A[M,K](bf16 rm) @ B[N,K](bf16 rm)^T (+Cadd). Optional bf16 output.
// Requires M%128==0, N%128==0, K%32==0.
#define BMM 128
#define BNN 128
#define BKK 32
#define BKP 40                      // padded halves per smem row (80B stride)
#define NSTG 3
#define STG_BYTES (BMM * BKP * 2)   // per array per stage = 10240B
#define BF_DSMEM (NSTG * 2 * STG_BYTES)

__device__ __forceinline__ uint32_t smem_u32(const void* p) {
    return (uint32_t)__cvta_generic_to_shared(p);
}

template<bool ADDC, bool OUTBF16>
__global__ void __launch_bounds__(128)
bf16gemm_k(const __nv_bfloat16* __restrict__ A,
           const __nv_bfloat16* __restrict__ B,
           float* __restrict__ C,
           __nv_bfloat16* __restrict__ Cb,
           const float* __restrict__ Cadd,
           float alpha, int Md, int Nd, int Kd)
{
    extern __shared__ __nv_bfloat16 dsm[];
    __nv_bfloat16* sAb = dsm;                        // NSTG stages of A
    __nv_bfloat16* sBb = dsm + NSTG * BMM * BKP;     // NSTG stages of B

    const int tid  = threadIdx.x;
    const int m0   = blockIdx.y * BMM;
    const int n0   = blockIdx.x * BNN;
    const int wid  = tid >> 5, lane = tid & 31;
    const int wr   = wid >> 1, wc = wid & 1;         // 2x2 warps, warp tile 64x64

    float acc[4][8][4];
#pragma unroll
    for (int mi = 0; mi < 4; mi++)
#pragma unroll
        for (int ni = 0; ni < 8; ni++)
#pragma unroll
            for (int q = 0; q < 4; q++) acc[mi][ni][q] = 0.f;

    const int KT = Kd / BKK;

    auto load_stage = [&](int s, int kt) {
        __nv_bfloat16* sa = sAb + s * BMM * BKP;
        __nv_bfloat16* sb = sBb + s * BNN * BKP;
#pragma unroll
        for (int i = 0; i < 4; i++) {
            int idx = tid + i * 128;                 // 0..511
            int r = idx >> 2, u = idx & 3;
            const __nv_bfloat16* g = A + (size_t)(m0 + r) * Kd + kt * BKK + u * 8;
            asm volatile("cp.async.ca.shared.global [%0], [%1], 16;\n"
                         :: "r"(smem_u32(&sa[r * BKP + u * 8])), "l"(g));
        }
#pragma unroll
        for (int i = 0; i < 4; i++) {
            int idx = tid + i * 128;
            int r = idx >> 2, u = idx & 3;
            const __nv_bfloat16* g = B + (size_t)(n0 + r) * Kd + kt * BKK + u * 8;
            asm volatile("cp.async.ca.shared.global [%0], [%1], 16;\n"
                         :: "r"(smem_u32(&sb[r * BKP + u * 8])), "l"(g));
        }
        asm volatile("cp.async.commit_group;\n");
    };

    load_stage(0, 0);
    load_stage(1, 1);

    for (int kt = 0; kt < KT; kt++) {
        const int s = kt % NSTG;
        if (kt + 1 < KT) { asm volatile("cp.async.wait_group 1;\n" ::: "memory"); }
        else             { asm volatile("cp.async.wait_group 0;\n" ::: "memory"); }
        __syncthreads();
        if (kt + 2 < KT) load_stage((kt + 2) % NSTG, kt + 2);

        const __nv_bfloat16* sa = sAb + s * BMM * BKP;
        const __nv_bfloat16* sb = sBb + s * BNN * BKP;

#pragma unroll
        for (int ks = 0; ks < 2; ks++) {
            uint32_t a[4][4], b[8][2];
#pragma unroll
            for (int mi = 0; mi < 4; mi++) {
                int row = wr * 64 + mi * 16 + (lane & 15);
                int col = ks * 16 + (lane >> 4) * 8;
                uint32_t addr = smem_u32(&sa[row * BKP + col]);
                asm volatile("ldmatrix.sync.aligned.m8n8.x4.shared.b16 {%0,%1,%2,%3}, [%4];\n"
                             : "=r"(a[mi][0]), "=r"(a[mi][1]), "=r"(a[mi][2]), "=r"(a[mi][3])
                             : "r"(addr));
            }
#pragma unroll
            for (int j = 0; j < 4; j++) {
                int n   = wc * 64 + j * 16 + (lane & 7) + ((lane >> 4) << 3);
                int col = ks * 16 + ((lane >> 3) & 1) * 8;
                uint32_t addr = smem_u32(&sb[n * BKP + col]);
                uint32_t r0, r1, r2, r3;
                asm volatile("ldmatrix.sync.aligned.m8n8.x4.shared.b16 {%0,%1,%2,%3}, [%4];\n"
                             : "=r"(r0), "=r"(r1), "=r"(r2), "=r"(r3) : "r"(addr));
                b[2 * j][0] = r0; b[2 * j][1] = r1;
                b[2 * j + 1][0] = r2; b[2 * j + 1][1] = r3;
            }
#pragma unroll
            for (int mi = 0; mi < 4; mi++)
#pragma unroll
                for (int ni = 0; ni < 8; ni++)
                    asm volatile(
                        "mma.sync.aligned.m16n8k16.row.col.f32.bf16.bf16.f32 "
                        "{%0,%1,%2,%3}, {%4,%5,%6,%7}, {%8,%9}, {%0,%1,%2,%3};\n"
                        : "+f"(acc[mi][ni][0]), "+f"(acc[mi][ni][1]),
                          "+f"(acc[mi][ni][2]), "+f"(acc[mi][ni][3])
                        : "r"(a[mi][0]), "r"(a[mi][1]), "r"(a[mi][2]), "r"(a[mi][3]),
                          "r"(b[ni][0]), "r"(b[ni][1]));
        }
        __syncthreads();
    }

    // epilogue
#pragma unroll
    for (int mi = 0; mi < 4; mi++) {
        int row = m0 + wr * 64 + mi * 16 + (lane >> 2);
#pragma unroll
        for (int ni = 0; ni < 8; ni++) {
            int col = n0 + wc * 64 + ni * 8 + (lane & 3) * 2;
            float2 lo = make_float2(acc[mi][ni][0] * alpha, acc[mi][ni][1] * alpha);
            float2 hi = make_float2(acc[mi][ni][2] * alpha, acc[mi][ni][3] * alpha);
            if (ADDC) {
                float2 c0 = *(const float2*)&Cadd[(size_t)row * Nd + col];
                float2 c1 = *(const float2*)&Cadd[(size_t)(row + 8) * Nd + col];
                lo.x += c0.x; lo.y += c0.y;
                hi.x += c1.x; hi.y += c1.y;
            }
            if (OUTBF16) {
                *(__nv_bfloat162*)&Cb[(size_t)row * Nd + col] =
                    __floats2bfloat162_rn(lo.x, lo.y);
                *(__nv_bfloat162*)&Cb[(size_t)(row + 8) * Nd + col] =
                    __floats2bfloat162_rn(hi.x, hi.y);
            } else {
                *(float2*)&C[(size_t)row * Nd + col]       = lo;
                *(float2*)&C[(size_t)(row + 8) * Nd + col] = hi;
            }
        }
    }
}

static inline void bf16gemm_f32(const __nv_bfloat16* A, const __nv_bfloat16* B,
                                float* C, const float* Cadd, float alpha,
                                int Md, int Nd, int Kd)
{
    dim3 grid(Nd / BNN, Md / BMM);
    if (Cadd) {
        cudaFuncSetAttribute(bf16gemm_k<true, false>,
                             cudaFuncAttributeMaxDynamicSharedMemorySize, BF_DSMEM);
        bf16gemm_k<true, false><<<grid, 128, BF_DSMEM>>>(A, B, C, nullptr, Cadd, alpha, Md, Nd, Kd);
    } else {
        cudaFuncSetAttribute(bf16gemm_k<false, false>,
                             cudaFuncAttributeMaxDynamicSharedMemorySize, BF_DSMEM);
        bf16gemm_k<false, false><<<grid, 128, BF_DSMEM>>>(A, B, C, nullptr, nullptr, alpha, Md, Nd, Kd);
    }
}

static inline void bf16gemm_b16(const __nv_bfloat16* A, const __nv_bfloat16* B,
                                __nv_bfloat16* Cb, float alpha,
                                int Md, int Nd, int Kd)
{
    dim3 grid(Nd / BNN, Md / BMM);
    cudaFuncSetAttribute(bf16gemm_k<false, true>,
                         cudaFuncAttributeMaxDynamicSharedMemorySize, BF_DSMEM);
    bf16gemm_k<false, true><<<grid, 128, BF_DSMEM>>>(A, B, nullptr, Cb, nullptr, alpha, Md, Nd, Kd);
}

// ---------------- conversions ----------------
__global__ void __launch_bounds__(256)
conv_k(const float4* __restrict__ in, __nv_bfloat162* __restrict__ out, int n4)
{
    int i = blockIdx.x * 256 + threadIdx.x;
    if (i < n4) {
        float4 v = in[i];
        out[2 * i]     = __floats2bfloat162_rn(v.x, v.y);
        out[2 * i + 1] = __floats2bfloat162_rn(v.z, v.w);
    }
}

// out[C][R] (bf16) = transpose of in[R][C] (f32). R,C multiples of 32.
__global__ void __launch_bounds__(256)
tconv_k(const float* __restrict__ in, __nv_bfloat16* __restrict__ out, int R, int C)
{
    __shared__ float t[32][33];
    int c0 = blockIdx.x * 32, r0 = blockIdx.y * 32;
    int x = threadIdx.x & 31, y = threadIdx.x >> 5;
#pragma unroll
    for (int j = 0; j < 32; j += 8)
        t[y + j][x] = in[(size_t)(r0 + y + j) * C + c0 + x];
    __syncthreads();
#pragma unroll
    for (int j = 0; j < 32; j += 8)
        out[(size_t)(c0 + y + j) * R + r0 + x] = __float2bfloat16(t[x][y + j]);
}

// ---------------- reductions ----------------
__device__ __forceinline__ float warpRedMax(float v) {
#pragma unroll
    for (int o = 16; o > 0; o >>= 1) v = fmaxf(v, __shfl_xor_sync(0xffffffffu, v, o));
    return v;
}
__device__ __forceinline__ float warpRedSum(float v) {
#pragma unroll
    for (int o = 16; o > 0; o >>= 1) v += __shfl_xor_sync(0xffffffffu, v, o);
    return v;
}
__device__ __forceinline__ float blockMax256(float v, float* red) {
    int lane = threadIdx.x & 31, w = threadIdx.x >> 5;
    v = warpRedMax(v);
    if (lane == 0) red[w] = v;
    __syncthreads();
    float r = red[0];
#pragma unroll
    for (int i = 1; i < 8; i++) r = fmaxf(r, red[i]);
    __syncthreads();
    return r;
}
__device__ __forceinline__ float blockSum256(float v, float* red) {
    int lane = threadIdx.x & 31, w = threadIdx.x >> 5;
    v = warpRedSum(v);
    if (lane == 0) red[w] = v;
    __syncthreads();
    float r = 0.f;
#pragma unroll
    for (int i = 0; i < 8; i++) r += red[i];
    __syncthreads();
    return r;
}

// ---------------- masked softmax ----------------
__global__ void __launch_bounds__(256)
softmax_k(float* __restrict__ S, const int* __restrict__ mask)
{
    __shared__ float red[8];
    const int l = blockIdx.x, h = blockIdx.y;
    float* row = S + (size_t)l * HK + (size_t)h * M_DIM;
    const int* mrow = mask + (size_t)l * M_DIM;
    const int t = threadIdx.x;

    float v[4];
    float mx = -3.4e38f;
#pragma unroll
    for (int i = 0; i < 4; i++) {
        int m = t + i * 256;
        float s = row[m];
        s = (mrow[m] != 0) ? s : -1e9f;
        v[i] = s;
        mx = fmaxf(mx, s);
    }
    mx = blockMax256(mx, red);
    float sum = 0.f;
#pragma unroll
    for (int i = 0; i < 4; i++) {
        float e = __expf(v[i] - mx);
        v[i] = e;
        sum += e;
    }
    sum = blockSum256(sum, red);
    float inv = __frcp_rn(sum);
#pragma unroll
    for (int i = 0; i < 4; i++) row[t + i * 256] = v[i] * inv;
}

// ---------------- layernorm ----------------
__global__ void __launch_bounds__(256)
ln_k(const float* __restrict__ x, const float* __restrict__ g, const float* __restrict__ be,
     float* __restrict__ out)
{
    __shared__ float red[8];
    const int r = blockIdx.x, t = threadIdx.x;
    float v = x[r * 256 + t];
    float mean = blockSum256(v, red) * (1.f / 256.f);
    float d = v - mean;
    float var = blockSum256(d * d, red) * (1.f / 256.f);
    out[r * 256 + t] = d * rsqrtf(var + EPS_LN) * g[t] + be[t];
}

// ---------------- launch ----------------
static inline void* symraw(const void* s) {
    void* p = nullptr;
    cudaGetSymbolAddress(&p, s);
    return p;
}

extern "C" void kernel_launch(void* const* d_in, const int* in_sizes, int n_in,
                              void* d_out, int out_size)
{
    (void)in_sizes; (void)n_in; (void)out_size;
    const float* Le    = (const float*)d_in[0];
    const float* Me    = (const float*)d_in[1];
    const float* Pe    = (const float*)d_in[2];
    const int*   maskL = (const int*)  d_in[3];
    const int*   maskP = (const int*)  d_in[4];
    const float *Wl  = (const float*)d_in[5],  *bl  = (const float*)d_in[6];
    const float *Wm  = (const float*)d_in[7],  *bm  = (const float*)d_in[8];
    const float *Wp  = (const float*)d_in[9],  *bp  = (const float*)d_in[10];
    const float *Wql = (const float*)d_in[11], *bql = (const float*)d_in[12];
    const float *Wkl = (const float*)d_in[13], *bkl = (const float*)d_in[14];
    const float *Wvl = (const float*)d_in[15], *bvl = (const float*)d_in[16];
    const float *Wqp = (const float*)d_in[17], *bqp = (const float*)d_in[18];
    const float *Wkp = (const float*)d_in[19], *bkp = (const float*)d_in[20];
    const float *Wvp = (const float*)d_in[21], *bvp = (const float*)d_in[22];
    const float *Wml = (const float*)d_in[23], *bml = (const float*)d_in[24];
    const float *Wmp = (const float*)d_in[25], *bmp = (const float*)d_in[26];
    const float *g1  = (const float*)d_in[27], *be1 = (const float*)d_in[28];
    const float *g2  = (const float*)d_in[29], *be2 = (const float*)d_in[30];

    float* lt   = (float*)symraw(g_lt);
    float* mt   = (float*)symraw(g_mt);
    float* pt   = (float*)symraw(g_pt);
    float* Ql   = (float*)symraw(g_Ql);
    float* Kl   = (float*)symraw(g_Kl);
    float* Vl   = (float*)symraw(g_Vl);
    float* Qp   = (float*)symraw(g_Qp);
    float* Kp   = (float*)symraw(g_Kp);
    float* Vp   = (float*)symraw(g_Vp);
    float* awl  = (float*)symraw(g_awl);
    float* awp  = (float*)symraw(g_awp);
    float* ctxl = (float*)symraw(g_ctxl);
    float* ctxp = (float*)symraw(g_ctxp);
    float* finl = (float*)symraw(g_finl);
    float* finp = (float*)symraw(g_finp);
    float* preL = (float*)symraw(g_preL);
    float* preP = (float*)symraw(g_preP);

    __nv_bfloat16* bawl   = (__nv_bfloat16*)symraw(g_bawl);
    __nv_bfloat16* bawlT  = (__nv_bfloat16*)symraw(g_bawlT);
    __nv_bfloat16* bawp   = (__nv_bfloat16*)symraw(g_bawp);
    __nv_bfloat16* bawpT  = (__nv_bfloat16*)symraw(g_bawpT);
    __nv_bfloat16* bctxlT = (__nv_bfloat16*)symraw(g_bctxlT);
    __nv_bfloat16* bctxpT = (__nv_bfloat16*)symraw(g_bctxpT);
    __nv_bfloat16* bTpT   = (__nv_bfloat16*)symraw(g_bTpT);
    __nv_bfloat16* bTlT   = (__nv_bfloat16*)symraw(g_bTlT);

    const float scale = 0.125f;   // 1/sqrt(DH)
    const float invH  = 0.125f;   // 1/H

    // 1) input projections
    gemm<false,false,false,false,true>(Le, HID, 0, Wl, HID, 0, lt, HID, 0, nullptr, 0, bl, 1.f, L_DIM, HID, HID, 1);
    gemm<false,false,false,false,true>(Me, HID, 0, Wm, HID, 0, mt, HID, 0, nullptr, 0, bm, 1.f, M_DIM, HID, HID, 1);
    gemm<false,false,false,false,true>(Pe, HID, 0, Wp, HID, 0, pt, HID, 0, nullptr, 0, bp, 1.f, P_DIM, HID, HID, 1);

    // 2) Q/K/V projections
    gemm<false,false,false,false,true>(lt, HID, 0, Wql, HID, 0, Ql, HID, 0, nullptr, 0, bql, 1.f, L_DIM, HID, HID, 1);
    gemm<false,false,false,false,true>(mt, HID, 0, Wkl, HID, 0, Kl, HID, 0, nullptr, 0, bkl, 1.f, M_DIM, HID, HID, 1);
    gemm<false,false,false,false,true>(mt, HID, 0, Wvl, HID, 0, Vl, HID, 0, nullptr, 0, bvl, 1.f, M_DIM, HID, HID, 1);
    gemm<false,false,false,false,true>(pt, HID, 0, Wqp, HID, 0, Qp, HID, 0, nullptr, 0, bqp, 1.f, P_DIM, HID, HID, 1);
    gemm<false,false,false,false,true>(mt, HID, 0, Wkp, HID, 0, Kp, HID, 0, nullptr, 0, bkp, 1.f, M_DIM, HID, HID, 1);
    gemm<false,false,false,false,true>(mt, HID, 0, Wvp, HID, 0, Vp, HID, 0, nullptr, 0, bvp, 1.f, M_DIM, HID, HID, 1);

    // 3) attention scores (batched over heads, NT, K=DH)
    gemm<false,true,false,false,false>(Ql, HID, DH, Kl, HID, DH, awl, HK, M_DIM, nullptr, 0, nullptr,
                                       scale, L_DIM, M_DIM, DH, NH);
    gemm<false,true,false,false,false>(Qp, HID, DH, Kp, HID, DH, awp, HK, M_DIM, nullptr, 0, nullptr,
                                       scale, P_DIM, M_DIM, DH, NH);

    // 4) masked softmax
    softmax_k<<<dim3(L_DIM, NH), 256>>>(awl, maskL);
    softmax_k<<<dim3(P_DIM, NH), 256>>>(awp, maskP);

    // 5) context (batched over heads, NN, relu)
    gemm<false,false,true,false,false>(awl, HK, M_DIM, Vl, HID, DH, ctxl, HID, DH, nullptr, 0, nullptr,
                                       1.f, L_DIM, DH, M_DIM, NH);
    gemm<false,false,true,false,false>(awp, HK, M_DIM, Vp, HID, DH, ctxp, HID, DH, nullptr, 0, nullptr,
                                       1.f, P_DIM, DH, M_DIM, NH);

    // 6) bf16 conversions for the mutual chain
    {
        int n4;
        n4 = (L_DIM * (HK / 4));
        conv_k<<<(n4 + 255) / 256, 256>>>((const float4*)awl, (__nv_bfloat162*)bawl, n4);
        n4 = (P_DIM * (HK / 4));
        conv_k<<<(n4 + 255) / 256, 256>>>((const float4*)awp, (__nv_bfloat162*)bawp, n4);
        tconv_k<<<dim3(HK / 32, L_DIM / 32), 256>>>(awl, bawlT, L_DIM, HK);
        tconv_k<<<dim3(HK / 32, P_DIM / 32), 256>>>(awp, bawpT, P_DIM, HK);
        tconv_k<<<dim3(HID / 32, L_DIM / 32), 256>>>(ctxl, bctxlT, L_DIM, HID);
        tconv_k<<<dim3(HID / 32, P_DIM / 32), 256>>>(ctxp, bctxpT, P_DIM, HID);
    }

    // 7) reassociated mutual via tensor cores (bf16-out T GEMMs, f32 fin GEMMs):
    //    bTpT[HID,HK] = ctxp^T @ awp  ;  finl = ctxl + (1/H) * awl @ bTpT^T
    //    bTlT[HID,HK] = ctxl^T @ awl  ;  finp = ctxp + (1/H) * awp @ bTlT^T
    bf16gemm_b16(bctxpT, bawpT, bTpT, 1.f, HID, HK, P_DIM);
    bf16gemm_f32(bawl, bTpT, finl, ctxl, invH, L_DIM, HID, HK);
    bf16gemm_b16(bctxlT, bawlT, bTlT, 1.f, HID, HK, L_DIM);
    bf16gemm_f32(bawp, bTlT, finp, ctxp, invH, P_DIM, HID, HK);

    // 8) final linears without concat: split-weight accumulating GEMMs
    //    preL = lt @ Wml[0:512] + bml ; preL += finl @ Wml[512:1024]
    gemm<false,false,false,false,true>(lt,   HID, 0, Wml,               DHALF, 0, preL, DHALF, 0,
                                       nullptr, 0, bml, 1.f, L_DIM, DHALF, HID, 1);
    gemm<false,false,false,true,false>(finl, HID, 0, Wml + HID * DHALF, DHALF, 0, preL, DHALF, 0,
                                       preL, DHALF, nullptr, 1.f, L_DIM, DHALF, HID, 1);
    //    preP = finp @ Wmp[0:512] + bmp ; preP += pt @ Wmp[512:1024]
    gemm<false,false,false,false,true>(finp, HID, 0, Wmp,               DHALF, 0, preP, DHALF, 0,
                                       nullptr, 0, bmp, 1.f, P_DIM, DHALF, HID, 1);
    gemm<false,false,false,true,false>(pt,   HID, 0, Wmp + HID * DHALF, DHALF, 0, preP, DHALF, 0,
                                       preP, DHALF, nullptr, 1.f, P_DIM, DHALF, HID, 1);

    // 9) layernorms -> output
    float* out = (float*)d_out;
    ln_k<<<L_DIM, 256>>>(preL, g1, be1, out);
    ln_k<<<P_DIM, 256>>>(preP, g2, be2, out + (size_t)L_DIM * DHALF);
}

// round 5
// speedup vs baseline: 3.6088x; 2.3103x over previous
#include <cuda_runtime.h>
#include <cuda_fp16.h>
#include <math.h>
#include <stdint.h>

// Problem constants
#define L_DIM 4096
#define M_DIM 1024
#define P_DIM 4096
#define HID   512
#define NH    8
#define DH    64
#define HK    (NH * M_DIM)   // 8192 flattened (h, m)
#define DHALF 256
#define EPS_LN 1e-5f

// ---------------- scratch (static device globals; no allocation) ----------------
__device__ float g_lt [L_DIM * HID];
__device__ float g_mt [M_DIM * HID];
__device__ float g_pt [P_DIM * HID];
__device__ float g_Ql [L_DIM * HID];
__device__ float g_Kl [M_DIM * HID];
__device__ float g_Vl [M_DIM * HID];
__device__ float g_Qp [P_DIM * HID];
__device__ float g_Kp [M_DIM * HID];
__device__ float g_Vp [M_DIM * HID];
__device__ float g_ctxl[L_DIM * HID];
__device__ float g_ctxp[P_DIM * HID];
__device__ float g_finl[L_DIM * HID];
__device__ float g_finp[P_DIM * HID];
__device__ float g_preL[L_DIM * DHALF];
__device__ float g_preP[P_DIM * DHALF];

// fp16 operand buffers
__device__ __half g_hQl [L_DIM * HID];
__device__ __half g_hKl [M_DIM * HID];
__device__ __half g_hQp [P_DIM * HID];
__device__ __half g_hKp [M_DIM * HID];
__device__ __half g_hVlT[HID * M_DIM];                // [HID][M]
__device__ __half g_hVpT[HID * M_DIM];
__device__ __half g_hawl [(size_t)L_DIM * HK];        // scores then softmaxed weights [L][HK]
__device__ __half g_hawlT[(size_t)HK * L_DIM];        // [HK][L]
__device__ __half g_hawp [(size_t)P_DIM * HK];
__device__ __half g_hawpT[(size_t)HK * P_DIM];
__device__ __half g_hctxlT[HID * L_DIM];              // [HID][L]
__device__ __half g_hctxpT[HID * P_DIM];
__device__ __half g_hTpT [HID * HK];                  // [HID][HK]
__device__ __half g_hTlT [HID * HK];

// ---------------- generic tiled SGEMM (fp32 path: projections + final linears) ----------------
template<bool RELU, bool ADDC, bool BIAS>
__global__ void __launch_bounds__(256, 2)
gemm_k(const float* __restrict__ A, int lda,
       const float* __restrict__ B, int ldb,
       float* __restrict__ C, int ldc,
       const float* __restrict__ Cadd, int ldadd,
       const float* __restrict__ bias,
       float alpha, int Md, int Nd, int Kd)
{
    __shared__ float As[16][129];
    __shared__ float Bs[16][129];

    const int row0 = blockIdx.y * 128;
    const int col0 = blockIdx.x * 128;
    const int tid  = threadIdx.x;
    const int tr   = tid >> 4;
    const int tc   = tid & 15;

    float acc[8][8];
#pragma unroll
    for (int i = 0; i < 8; i++)
#pragma unroll
        for (int j = 0; j < 8; j++) acc[i][j] = 0.f;

    for (int k0 = 0; k0 < Kd; k0 += 16) {
#pragma unroll
        for (int i = 0; i < 8; i++) {
            int idx = tid + i * 256;
            int k = idx & 15, m = idx >> 4;
            int gm = row0 + m;
            float v = 0.f;
            if (gm < Md) v = A[(long)gm * lda + k0 + k];
            As[k][m] = v;
        }
#pragma unroll
        for (int i = 0; i < 8; i++) {
            int idx = tid + i * 256;
            int n = idx & 127, k = idx >> 7;
            int gn = col0 + n;
            float v = 0.f;
            if (gn < Nd) v = B[(long)(k0 + k) * ldb + gn];
            Bs[k][n] = v;
        }
        __syncthreads();

#pragma unroll
        for (int k = 0; k < 16; k++) {
            float ra[8], rb[8];
#pragma unroll
            for (int i = 0; i < 8; i++) ra[i] = As[k][tr * 8 + i];
#pragma unroll
            for (int j = 0; j < 8; j++) rb[j] = Bs[k][tc * 8 + j];
#pragma unroll
            for (int i = 0; i < 8; i++)
#pragma unroll
                for (int j = 0; j < 8; j++)
                    acc[i][j] = fmaf(ra[i], rb[j], acc[i][j]);
        }
        __syncthreads();
    }

#pragma unroll
    for (int i = 0; i < 8; i++) {
        int gm = row0 + tr * 8 + i;
        if (gm >= Md) continue;
#pragma unroll
        for (int j = 0; j < 8; j++) {
            int gn = col0 + tc * 8 + j;
            if (gn >= Nd) continue;
            float v = acc[i][j] * alpha;
            if (BIAS) v += bias[gn];
            if (ADDC) v += Cadd[(long)gm * ldadd + gn];
            if (RELU) v = fmaxf(v, 0.f);
            C[(long)gm * ldc + gn] = v;
        }
    }
}

template<bool RELU, bool ADDC, bool BIAS>
static inline void gemm(const float* A, int lda, const float* B, int ldb,
                        float* C, int ldc, const float* Cadd, int ldadd,
                        const float* bias, float alpha, int Md, int Nd, int Kd)
{
    dim3 grid((Nd + 127) / 128, (Md + 127) / 128);
    gemm_k<RELU, ADDC, BIAS><<<grid, 256>>>(A, lda, B, ldb, C, ldc, Cadd, ldadd, bias,
                                            alpha, Md, Nd, Kd);
}

// ================= fp16 tensor-core GEMM (mma.sync, 3-stage, strided/batched) =================
// C[M,N] = alpha * A[M,K](f16, row ld=lda) @ B[N,K](f16, row ld=ldb)^T (+Cadd) (relu)
// Requires M%128==0, N%BN==0, K%32==0. No bounds checks (all shapes are exact multiples).
#define HPAD 40

__device__ __forceinline__ uint32_t smem_u32(const void* p) {
    return (uint32_t)__cvta_generic_to_shared(p);
}

template<int BN, bool RELU, bool ADDC, bool OUTF16>
__global__ void __launch_bounds__(256)
hgemm_k(const __half* __restrict__ A, int lda, long sA,
        const __half* __restrict__ B, int ldb, long sB,
        float* __restrict__ C, __half* __restrict__ Ch, int ldc, long sC,
        const float* __restrict__ Cadd, int ldadd, long sAdd,
        float alpha, int Md, int Nd, int Kd)
{
    constexpr int BM = 128;
    constexpr int WN = BN / 32;          // warps along N
    constexpr int WM = 8 / WN;           // warps along M
    constexpr int MI = BM / (WM * 16);   // m16 fragments per warp
    constexpr int NI = 4;                // n8 fragments per warp (32 cols)

    extern __shared__ __half hsm[];
    __half* sAb = hsm;                   // 3 stages x BM*HPAD
    __half* sBb = hsm + 3 * BM * HPAD;   // 3 stages x BN*HPAD

    const int tid  = threadIdx.x;
    const int wid  = tid >> 5, lane = tid & 31;
    const int wr   = wid / WN, wc = wid % WN;
    const int m0   = blockIdx.y * BM;
    const int n0   = blockIdx.x * BN;
    const long z   = blockIdx.z;

    A += z * sA;
    B += z * sB;

    float acc[MI][NI][4];
#pragma unroll
    for (int mi = 0; mi < MI; mi++)
#pragma unroll
        for (int ni = 0; ni < NI; ni++)
#pragma unroll
            for (int q = 0; q < 4; q++) acc[mi][ni][q] = 0.f;

    const int KT = Kd / 32;

    auto load_stage = [&](int s, int kt) {
        __half* sa = sAb + s * BM * HPAD;
        __half* sb = sBb + s * BN * HPAD;
#pragma unroll
        for (int i = 0; i < (BM * 4) / 256; i++) {
            int idx = tid + i * 256;
            int r = idx >> 2, u = idx & 3;
            const __half* g = A + (size_t)(m0 + r) * lda + kt * 32 + u * 8;
            asm volatile("cp.async.ca.shared.global [%0], [%1], 16;\n"
                         :: "r"(smem_u32(&sa[r * HPAD + u * 8])), "l"(g));
        }
#pragma unroll
        for (int i = 0; i < (BN * 4) / 256; i++) {
            int idx = tid + i * 256;
            int r = idx >> 2, u = idx & 3;
            const __half* g = B + (size_t)(n0 + r) * ldb + kt * 32 + u * 8;
            asm volatile("cp.async.ca.shared.global [%0], [%1], 16;\n"
                         :: "r"(smem_u32(&sb[r * HPAD + u * 8])), "l"(g));
        }
        asm volatile("cp.async.commit_group;\n");
    };

    load_stage(0, 0);
    if (KT > 1) load_stage(1, 1);
    else        asm volatile("cp.async.commit_group;\n");   // keep group count consistent

    for (int kt = 0; kt < KT; kt++) {
        const int s = kt % 3;
        if (kt + 1 < KT) { asm volatile("cp.async.wait_group 1;\n" ::: "memory"); }
        else             { asm volatile("cp.async.wait_group 0;\n" ::: "memory"); }
        __syncthreads();
        if (kt + 2 < KT) load_stage((kt + 2) % 3, kt + 2);

        const __half* sa = sAb + s * BM * HPAD;
        const __half* sb = sBb + s * BN * HPAD;

#pragma unroll
        for (int ks = 0; ks < 2; ks++) {
            uint32_t a[MI][4], b[NI][2];
#pragma unroll
            for (int mi = 0; mi < MI; mi++) {
                int row = wr * (MI * 16) + mi * 16 + (lane & 15);
                int col = ks * 16 + (lane >> 4) * 8;
                uint32_t addr = smem_u32(&sa[row * HPAD + col]);
                asm volatile("ldmatrix.sync.aligned.m8n8.x4.shared.b16 {%0,%1,%2,%3}, [%4];\n"
                             : "=r"(a[mi][0]), "=r"(a[mi][1]), "=r"(a[mi][2]), "=r"(a[mi][3])
                             : "r"(addr));
            }
#pragma unroll
            for (int j = 0; j < NI / 2; j++) {
                int n   = wc * 32 + j * 16 + (lane & 7) + ((lane >> 4) << 3);
                int col = ks * 16 + ((lane >> 3) & 1) * 8;
                uint32_t addr = smem_u32(&sb[n * HPAD + col]);
                uint32_t r0, r1, r2, r3;
                asm volatile("ldmatrix.sync.aligned.m8n8.x4.shared.b16 {%0,%1,%2,%3}, [%4];\n"
                             : "=r"(r0), "=r"(r1), "=r"(r2), "=r"(r3) : "r"(addr));
                b[2 * j][0] = r0; b[2 * j][1] = r1;
                b[2 * j + 1][0] = r2; b[2 * j + 1][1] = r3;
            }
#pragma unroll
            for (int mi = 0; mi < MI; mi++)
#pragma unroll
                for (int ni = 0; ni < NI; ni++)
                    asm volatile(
                        "mma.sync.aligned.m16n8k16.row.col.f32.f16.f16.f32 "
                        "{%0,%1,%2,%3}, {%4,%5,%6,%7}, {%8,%9}, {%0,%1,%2,%3};\n"
                        : "+f"(acc[mi][ni][0]), "+f"(acc[mi][ni][1]),
                          "+f"(acc[mi][ni][2]), "+f"(acc[mi][ni][3])
                        : "r"(a[mi][0]), "r"(a[mi][1]), "r"(a[mi][2]), "r"(a[mi][3]),
                          "r"(b[ni][0]), "r"(b[ni][1]));
        }
        __syncthreads();
    }

    // epilogue
#pragma unroll
    for (int mi = 0; mi < MI; mi++) {
        int row = m0 + wr * (MI * 16) + mi * 16 + (lane >> 2);
#pragma unroll
        for (int ni = 0; ni < NI; ni++) {
            int col = n0 + wc * 32 + ni * 8 + (lane & 3) * 2;
            float2 lo = make_float2(acc[mi][ni][0] * alpha, acc[mi][ni][1] * alpha);
            float2 hi = make_float2(acc[mi][ni][2] * alpha, acc[mi][ni][3] * alpha);
            if (ADDC) {
                const float* ca = Cadd + z * sAdd;
                float2 c0 = *(const float2*)&ca[(size_t)row * ldadd + col];
                float2 c1 = *(const float2*)&ca[(size_t)(row + 8) * ldadd + col];
                lo.x += c0.x; lo.y += c0.y;
                hi.x += c1.x; hi.y += c1.y;
            }
            if (RELU) {
                lo.x = fmaxf(lo.x, 0.f); lo.y = fmaxf(lo.y, 0.f);
                hi.x = fmaxf(hi.x, 0.f); hi.y = fmaxf(hi.y, 0.f);
            }
            if (OUTF16) {
                __half* co = Ch + z * sC;
                *(__half2*)&co[(size_t)row * ldc + col]       = __floats2half2_rn(lo.x, lo.y);
                *(__half2*)&co[(size_t)(row + 8) * ldc + col] = __floats2half2_rn(hi.x, hi.y);
            } else {
                float* co = C + z * sC;
                *(float2*)&co[(size_t)row * ldc + col]       = lo;
                *(float2*)&co[(size_t)(row + 8) * ldc + col] = hi;
            }
        }
    }
}

template<int BN, bool RELU, bool ADDC, bool OUTF16>
static inline void hgemm(const __half* A, int lda, long sA,
                         const __half* B, int ldb, long sB,
                         float* C, __half* Ch, int ldc, long sC,
                         const float* Cadd, int ldadd, long sAdd,
                         float alpha, int Md, int Nd, int Kd, int batch)
{
    constexpr int SMEM = 3 * (128 + BN) * HPAD * 2;
    cudaFuncSetAttribute(hgemm_k<BN, RELU, ADDC, OUTF16>,
                         cudaFuncAttributeMaxDynamicSharedMemorySize, SMEM);
    dim3 grid(Nd / BN, Md / 128, batch);
    hgemm_k<BN, RELU, ADDC, OUTF16><<<grid, 256, SMEM>>>(
        A, lda, sA, B, ldb, sB, C, Ch, ldc, sC, Cadd, ldadd, sAdd, alpha, Md, Nd, Kd);
}

// ---------------- conversions ----------------
__global__ void __launch_bounds__(256)
conv_k(const float4* __restrict__ in, __half2* __restrict__ out, int n4)
{
    int i = blockIdx.x * 256 + threadIdx.x;
    if (i < n4) {
        float4 v = in[i];
        out[2 * i]     = __floats2half2_rn(v.x, v.y);
        out[2 * i + 1] = __floats2half2_rn(v.z, v.w);
    }
}

// out[C][R] (f16) = transpose of in[R][C] (f32). R,C multiples of 32.
__global__ void __launch_bounds__(256)
tconv_f2h_k(const float* __restrict__ in, __half* __restrict__ out, int R, int C)
{
    __shared__ float t[32][33];
    int c0 = blockIdx.x * 32, r0 = blockIdx.y * 32;
    int x = threadIdx.x & 31, y = threadIdx.x >> 5;
#pragma unroll
    for (int j = 0; j < 32; j += 8)
        t[y + j][x] = in[(size_t)(r0 + y + j) * C + c0 + x];
    __syncthreads();
#pragma unroll
    for (int j = 0; j < 32; j += 8)
        out[(size_t)(c0 + y + j) * R + r0 + x] = __float2half(t[x][y + j]);
}

// out[C][R] (f16) = transpose of in[R][C] (f16). R,C multiples of 32.
__global__ void __launch_bounds__(256)
tconv_h2h_k(const __half* __restrict__ in, __half* __restrict__ out, int R, int C)
{
    __shared__ __half t[32][34];
    int c0 = blockIdx.x * 32, r0 = blockIdx.y * 32;
    int x = threadIdx.x & 31, y = threadIdx.x >> 5;
#pragma unroll
    for (int j = 0; j < 32; j += 8)
        t[y + j][x] = in[(size_t)(r0 + y + j) * C + c0 + x];
    __syncthreads();
#pragma unroll
    for (int j = 0; j < 32; j += 8)
        out[(size_t)(c0 + y + j) * R + r0 + x] = t[x][y + j];
}

// ---------------- reductions ----------------
__device__ __forceinline__ float warpRedMax(float v) {
#pragma unroll
    for (int o = 16; o > 0; o >>= 1) v = fmaxf(v, __shfl_xor_sync(0xffffffffu, v, o));
    return v;
}
__device__ __forceinline__ float warpRedSum(float v) {
#pragma unroll
    for (int o = 16; o > 0; o >>= 1) v += __shfl_xor_sync(0xffffffffu, v, o);
    return v;
}
__device__ __forceinline__ float blockMax256(float v, float* red) {
    int lane = threadIdx.x & 31, w = threadIdx.x >> 5;
    v = warpRedMax(v);
    if (lane == 0) red[w] = v;
    __syncthreads();
    float r = red[0];
#pragma unroll
    for (int i = 1; i < 8; i++) r = fmaxf(r, red[i]);
    __syncthreads();
    return r;
}
__device__ __forceinline__ float blockSum256(float v, float* red) {
    int lane = threadIdx.x & 31, w = threadIdx.x >> 5;
    v = warpRedSum(v);
    if (lane == 0) red[w] = v;
    __syncthreads();
    float r = 0.f;
#pragma unroll
    for (int i = 0; i < 8; i++) r += red[i];
    __syncthreads();
    return r;
}

// ---------------- masked softmax, in place on fp16 scores ----------------
__global__ void __launch_bounds__(256)
softmax16_k(__half* __restrict__ S, const int* __restrict__ mask)
{
    __shared__ float red[8];
    const int l = blockIdx.x, h = blockIdx.y;
    __half* row = S + (size_t)l * HK + (size_t)h * M_DIM;
    const int* mrow = mask + (size_t)l * M_DIM;
    const int t = threadIdx.x;

    float v[4];
    float mx = -3.4e38f;
#pragma unroll
    for (int i = 0; i < 4; i++) {
        int m = t + i * 256;
        float s = __half2float(row[m]);
        s = (mrow[m] != 0) ? s : -1e9f;
        v[i] = s;
        mx = fmaxf(mx, s);
    }
    mx = blockMax256(mx, red);
    float sum = 0.f;
#pragma unroll
    for (int i = 0; i < 4; i++) {
        float e = __expf(v[i] - mx);
        v[i] = e;
        sum += e;
    }
    sum = blockSum256(sum, red);
    float inv = __frcp_rn(sum);
#pragma unroll
    for (int i = 0; i < 4; i++) row[t + i * 256] = __float2half(v[i] * inv);
}

// ---------------- layernorm ----------------
__global__ void __launch_bounds__(256)
ln_k(const float* __restrict__ x, const float* __restrict__ g, const float* __restrict__ be,
     float* __restrict__ out)
{
    __shared__ float red[8];
    const int r = blockIdx.x, t = threadIdx.x;
    float v = x[r * 256 + t];
    float mean = blockSum256(v, red) * (1.f / 256.f);
    float d = v - mean;
    float var = blockSum256(d * d, red) * (1.f / 256.f);
    out[r * 256 + t] = d * rsqrtf(var + EPS_LN) * g[t] + be[t];
}

// ---------------- launch ----------------
static inline void* symraw(const void* s) {
    void* p = nullptr;
    cudaGetSymbolAddress(&p, s);
    return p;
}

extern "C" void kernel_launch(void* const* d_in, const int* in_sizes, int n_in,
                              void* d_out, int out_size)
{
    (void)in_sizes; (void)n_in; (void)out_size;
    const float* Le    = (const float*)d_in[0];
    const float* Me    = (const float*)d_in[1];
    const float* Pe    = (const float*)d_in[2];
    const int*   maskL = (const int*)  d_in[3];
    const int*   maskP = (const int*)  d_in[4];
    const float *Wl  = (const float*)d_in[5],  *bl  = (const float*)d_in[6];
    const float *Wm  = (const float*)d_in[7],  *bm  = (const float*)d_in[8];
    const float *Wp  = (const float*)d_in[9],  *bp  = (const float*)d_in[10];
    const float *Wql = (const float*)d_in[11], *bql = (const float*)d_in[12];
    const float *Wkl = (const float*)d_in[13], *bkl = (const float*)d_in[14];
    const float *Wvl = (const float*)d_in[15], *bvl = (const float*)d_in[16];
    const float *Wqp = (const float*)d_in[17], *bqp = (const float*)d_in[18];
    const float *Wkp = (const float*)d_in[19], *bkp = (const float*)d_in[20];
    const float *Wvp = (const float*)d_in[21], *bvp = (const float*)d_in[22];
    const float *Wml = (const float*)d_in[23], *bml = (const float*)d_in[24];
    const float *Wmp = (const float*)d_in[25], *bmp = (const float*)d_in[26];
    const float *g1  = (const float*)d_in[27], *be1 = (const float*)d_in[28];
    const float *g2  = (const float*)d_in[29], *be2 = (const float*)d_in[30];

    float* lt   = (float*)symraw(g_lt);
    float* mt   = (float*)symraw(g_mt);
    float* pt   = (float*)symraw(g_pt);
    float* Ql   = (float*)symraw(g_Ql);
    float* Kl   = (float*)symraw(g_Kl);
    float* Vl   = (float*)symraw(g_Vl);
    float* Qp   = (float*)symraw(g_Qp);
    float* Kp   = (float*)symraw(g_Kp);
    float* Vp   = (float*)symraw(g_Vp);
    float* ctxl = (float*)symraw(g_ctxl);
    float* ctxp = (float*)symraw(g_ctxp);
    float* finl = (float*)symraw(g_finl);
    float* finp = (float*)symraw(g_finp);
    float* preL = (float*)symraw(g_preL);
    float* preP = (float*)symraw(g_preP);

    __half* hQl   = (__half*)symraw(g_hQl);
    __half* hKl   = (__half*)symraw(g_hKl);
    __half* hQp   = (__half*)symraw(g_hQp);
    __half* hKp   = (__half*)symraw(g_hKp);
    __half* hVlT  = (__half*)symraw(g_hVlT);
    __half* hVpT  = (__half*)symraw(g_hVpT);
    __half* hawl  = (__half*)symraw(g_hawl);
    __half* hawlT = (__half*)symraw(g_hawlT);
    __half* hawp  = (__half*)symraw(g_hawp);
    __half* hawpT = (__half*)symraw(g_hawpT);
    __half* hctxlT= (__half*)symraw(g_hctxlT);
    __half* hctxpT= (__half*)symraw(g_hctxpT);
    __half* hTpT  = (__half*)symraw(g_hTpT);
    __half* hTlT  = (__half*)symraw(g_hTlT);

    const float scale = 0.125f;   // 1/sqrt(DH)
    const float invH  = 0.125f;   // 1/H

    // 1) input projections (fp32)
    gemm<false,false,true>(Le, HID, Wl, HID, lt, HID, nullptr, 0, bl, 1.f, L_DIM, HID, HID);
    gemm<false,false,true>(Me, HID, Wm, HID, mt, HID, nullptr, 0, bm, 1.f, M_DIM, HID, HID);
    gemm<false,false,true>(Pe, HID, Wp, HID, pt, HID, nullptr, 0, bp, 1.f, P_DIM, HID, HID);

    // 2) Q/K/V projections (fp32)
    gemm<false,false,true>(lt, HID, Wql, HID, Ql, HID, nullptr, 0, bql, 1.f, L_DIM, HID, HID);
    gemm<false,false,true>(mt, HID, Wkl, HID, Kl, HID, nullptr, 0, bkl, 1.f, M_DIM, HID, HID);
    gemm<false,false,true>(mt, HID, Wvl, HID, Vl, HID, nullptr, 0, bvl, 1.f, M_DIM, HID, HID);
    gemm<false,false,true>(pt, HID, Wqp, HID, Qp, HID, nullptr, 0, bqp, 1.f, P_DIM, HID, HID);
    gemm<false,false,true>(mt, HID, Wkp, HID, Kp, HID, nullptr, 0, bkp, 1.f, M_DIM, HID, HID);
    gemm<false,false,true>(mt, HID, Wvp, HID, Vp, HID, nullptr, 0, bvp, 1.f, M_DIM, HID, HID);

    // 3) fp16 conversions of Q/K (+ V transposed for context GEMM)
    conv_k<<<(L_DIM * HID / 4 + 255) / 256, 256>>>((const float4*)Ql, (__half2*)hQl, L_DIM * HID / 4);
    conv_k<<<(M_DIM * HID / 4 + 255) / 256, 256>>>((const float4*)Kl, (__half2*)hKl, M_DIM * HID / 4);
    conv_k<<<(P_DIM * HID / 4 + 255) / 256, 256>>>((const float4*)Qp, (__half2*)hQp, P_DIM * HID / 4);
    conv_k<<<(M_DIM * HID / 4 + 255) / 256, 256>>>((const float4*)Kp, (__half2*)hKp, M_DIM * HID / 4);
    tconv_f2h_k<<<dim3(HID / 32, M_DIM / 32), 256>>>(Vl, hVlT, M_DIM, HID);
    tconv_f2h_k<<<dim3(HID / 32, M_DIM / 32), 256>>>(Vp, hVpT, M_DIM, HID);

    // 4) attention scores (tensor cores, batched over heads) -> fp16 score buffer
    hgemm<128,false,false,true>(hQl, HID, DH, hKl, HID, DH,
                                nullptr, hawl, HK, M_DIM, nullptr, 0, 0,
                                scale, L_DIM, M_DIM, DH, NH);
    hgemm<128,false,false,true>(hQp, HID, DH, hKp, HID, DH,
                                nullptr, hawp, HK, M_DIM, nullptr, 0, 0,
                                scale, P_DIM, M_DIM, DH, NH);

    // 5) masked softmax, in place (fp16 in/out, f32 math)
    softmax16_k<<<dim3(L_DIM, NH), 256>>>(hawl, maskL);
    softmax16_k<<<dim3(P_DIM, NH), 256>>>(hawp, maskP);

    // 6) context (tensor cores, BN=64, relu fused) -> f32 ctx
    hgemm<64,true,false,false>(hawl, HK, M_DIM, hVlT, M_DIM, (long)DH * M_DIM,
                               ctxl, nullptr, HID, DH, nullptr, 0, 0,
                               1.f, L_DIM, DH, M_DIM, NH);
    hgemm<64,true,false,false>(hawp, HK, M_DIM, hVpT, M_DIM, (long)DH * M_DIM,
                               ctxp, nullptr, HID, DH, nullptr, 0, 0,
                               1.f, P_DIM, DH, M_DIM, NH);

    // 7) transposed fp16 copies for the mutual chain
    tconv_h2h_k<<<dim3(HK / 32, L_DIM / 32), 256>>>(hawl, hawlT, L_DIM, HK);
    tconv_h2h_k<<<dim3(HK / 32, P_DIM / 32), 256>>>(hawp, hawpT, P_DIM, HK);
    tconv_f2h_k<<<dim3(HID / 32, L_DIM / 32), 256>>>(ctxl, hctxlT, L_DIM, HID);
    tconv_f2h_k<<<dim3(HID / 32, P_DIM / 32), 256>>>(ctxp, hctxpT, P_DIM, HID);

    // 8) reassociated mutual (tensor cores):
    //    hTpT[HID,HK] = ctxp^T @ awp ;  finl = ctxl + (1/H) * awl @ hTpT^T
    //    hTlT[HID,HK] = ctxl^T @ awl ;  finp = ctxp + (1/H) * awp @ hTlT^T
    hgemm<128,false,false,true>(hctxpT, P_DIM, 0, hawpT, P_DIM, 0,
                                nullptr, hTpT, HK, 0, nullptr, 0, 0,
                                1.f, HID, HK, P_DIM, 1);
    hgemm<128,false,true,false>(hawl, HK, 0, hTpT, HK, 0,
                                finl, nullptr, HID, 0, ctxl, HID, 0,
                                invH, L_DIM, HID, HK, 1);
    hgemm<128,false,false,true>(hctxlT, L_DIM, 0, hawlT, L_DIM, 0,
                                nullptr, hTlT, HK, 0, nullptr, 0, 0,
                                1.f, HID, HK, L_DIM, 1);
    hgemm<128,false,true,false>(hawp, HK, 0, hTlT, HK, 0,
                                finp, nullptr, HID, 0, ctxp, HID, 0,
                                invH, P_DIM, HID, HK, 1);

    // 9) final linears (fp32, split-weight accumulate; no concat)
    gemm<false,false,true>(lt,   HID, Wml,               DHALF, preL, DHALF, nullptr, 0, bml,
                           1.f, L_DIM, DHALF, HID);
    gemm<false,true,false>(finl, HID, Wml + HID * DHALF, DHALF, preL, DHALF, preL, DHALF, nullptr,
                           1.f, L_DIM, DHALF, HID);
    gemm<false,false,true>(finp, HID, Wmp,               DHALF, preP, DHALF, nullptr, 0, bmp,
                           1.f, P_DIM, DHALF, HID);
    gemm<false,true,false>(pt,   HID, Wmp + HID * DHALF, DHALF, preP, DHALF, preP, DHALF, nullptr,
                           1.f, P_DIM, DHALF, HID);

    // 10) layernorms -> output
    float* out = (float*)d_out;
    ln_k<<<L_DIM, 256>>>(preL, g1, be1, out);
    ln_k<<<P_DIM, 256>>>(preP, g2, be2, out + (size_t)L_DIM * DHALF);
}

// round 7
// speedup vs baseline: 7.3012x; 2.0232x over previous
#include <cuda_runtime.h>
#include <cuda_fp16.h>
#include <math.h>
#include <stdint.h>

// Problem constants
#define L_DIM 4096
#define M_DIM 1024
#define P_DIM 4096
#define HID   512
#define NH    8
#define DH    64
#define HK    (NH * M_DIM)   // 8192 flattened (h, m)
#define DHALF 256
#define EPS_LN 1e-5f

// ---------------- scratch (static device globals; no allocation) ----------------
__device__ float g_preL[L_DIM * DHALF];
__device__ float g_preP[P_DIM * DHALF];

// fp16 inputs / weights (transposed [N][K])
__device__ __half g_hLe [L_DIM * HID];
__device__ __half g_hMe [M_DIM * HID];
__device__ __half g_hPe [P_DIM * HID];
__device__ __half g_hWlT [HID * HID];
__device__ __half g_hWmT [HID * HID];
__device__ __half g_hWpT [HID * HID];
__device__ __half g_hWqlT[HID * HID];
__device__ __half g_hWklT[HID * HID];
__device__ __half g_hWvlT[HID * HID];
__device__ __half g_hWqpT[HID * HID];
__device__ __half g_hWkpT[HID * HID];
__device__ __half g_hWvpT[HID * HID];
__device__ __half g_hWmlT[DHALF * 2 * HID];   // [256][1024]
__device__ __half g_hWmpT[DHALF * 2 * HID];

// fp16 activations
__device__ __half g_hlt [L_DIM * HID];
__device__ __half g_hmt [M_DIM * HID];
__device__ __half g_hpt [P_DIM * HID];
__device__ __half g_hQl [L_DIM * HID];
__device__ __half g_hKl [M_DIM * HID];
__device__ __half g_hQp [P_DIM * HID];
__device__ __half g_hKp [M_DIM * HID];
__device__ __half g_hVlT[HID * M_DIM];                // [HID][M]
__device__ __half g_hVpT[HID * M_DIM];
__device__ __half g_hawl [(size_t)L_DIM * HK];        // scores -> softmaxed weights
__device__ __half g_hawlT[(size_t)HK * L_DIM];
__device__ __half g_hawp [(size_t)P_DIM * HK];
__device__ __half g_hawpT[(size_t)HK * P_DIM];
__device__ __half g_hctxl[L_DIM * HID];
__device__ __half g_hctxp[P_DIM * HID];
__device__ __half g_hctxlT[HID * L_DIM];
__device__ __half g_hctxpT[HID * P_DIM];
__device__ __half g_hTpT [HID * HK];                  // [HID][HK]
__device__ __half g_hTlT [HID * HK];
__device__ __half g_hfinl[L_DIM * HID];
__device__ __half g_hfinp[P_DIM * HID];

// ================= fp16 tensor-core GEMM (mma.sync, 3-stage, strided/batched) =================
// C[M,N] = alpha * A[M,K](f16, ld=lda) @ B[N,K](f16, ld=ldb)^T  (+bias) (+Cadd) (relu)
// CADDM: 0 none, 1 f32 Cadd, 2 f16 Cadd.  BIASM: 0 none, 1 per-col, 2 per-row.
// Requires M%128==0, N%BN==0, K%32==0 (all call sites exact).
#define HPAD 40

__device__ __forceinline__ uint32_t smem_u32(const void* p) {
    return (uint32_t)__cvta_generic_to_shared(p);
}

template<int BN, bool RELU, int CADDM, bool OUTF16, int BIASM>
__global__ void __launch_bounds__(256)
hgemm_k(const __half* __restrict__ A, int lda, long sA,
        const __half* __restrict__ B, int ldb, long sB,
        float* __restrict__ C, __half* __restrict__ Ch, int ldc, long sC,
        const float* __restrict__ CaddF, const __half* __restrict__ CaddH,
        int ldadd, long sAdd,
        const float* __restrict__ bias,
        float alpha, int Md, int Nd, int Kd)
{
    constexpr int BM = 128;
    constexpr int WN = BN / 32;          // warps along N
    constexpr int WM = 8 / WN;           // warps along M
    constexpr int MI = BM / (WM * 16);   // m16 fragments per warp
    constexpr int NI = 4;                // n8 fragments per warp (32 cols)

    extern __shared__ __half hsm[];
    __half* sAb = hsm;                   // 3 stages x BM*HPAD
    __half* sBb = hsm + 3 * BM * HPAD;   // 3 stages x BN*HPAD

    const int tid  = threadIdx.x;
    const int wid  = tid >> 5, lane = tid & 31;
    const int wr   = wid / WN, wc = wid % WN;
    const int m0   = blockIdx.y * BM;
    const int n0   = blockIdx.x * BN;
    const long z   = blockIdx.z;

    A += z * sA;
    B += z * sB;

    float acc[MI][NI][4];
#pragma unroll
    for (int mi = 0; mi < MI; mi++)
#pragma unroll
        for (int ni = 0; ni < NI; ni++)
#pragma unroll
            for (int q = 0; q < 4; q++) acc[mi][ni][q] = 0.f;

    const int KT = Kd / 32;

    auto load_stage = [&](int s, int kt) {
        __half* sa = sAb + s * BM * HPAD;
        __half* sb = sBb + s * BN * HPAD;
#pragma unroll
        for (int i = 0; i < (BM * 4) / 256; i++) {
            int idx = tid + i * 256;
            int r = idx >> 2, u = idx & 3;
            const __half* g = A + (size_t)(m0 + r) * lda + kt * 32 + u * 8;
            asm volatile("cp.async.ca.shared.global [%0], [%1], 16;\n"
                         :: "r"(smem_u32(&sa[r * HPAD + u * 8])), "l"(g));
        }
#pragma unroll
        for (int i = 0; i < (BN * 4) / 256; i++) {
            int idx = tid + i * 256;
            int r = idx >> 2, u = idx & 3;
            const __half* g = B + (size_t)(n0 + r) * ldb + kt * 32 + u * 8;
            asm volatile("cp.async.ca.shared.global [%0], [%1], 16;\n"
                         :: "r"(smem_u32(&sb[r * HPAD + u * 8])), "l"(g));
        }
        asm volatile("cp.async.commit_group;\n");
    };

    load_stage(0, 0);
    load_stage(1, 1);        // KT >= 2 at every call site

    for (int kt = 0; kt < KT; kt++) {
        const int s = kt % 3;
        if (kt + 1 < KT) { asm volatile("cp.async.wait_group 1;\n" ::: "memory"); }
        else             { asm volatile("cp.async.wait_group 0;\n" ::: "memory"); }
        __syncthreads();
        if (kt + 2 < KT) load_stage((kt + 2) % 3, kt + 2);

        const __half* sa = sAb + s * BM * HPAD;
        const __half* sb = sBb + s * BN * HPAD;

#pragma unroll
        for (int ks = 0; ks < 2; ks++) {
            uint32_t a[MI][4], b[NI][2];
#pragma unroll
            for (int mi = 0; mi < MI; mi++) {
                int row = wr * (MI * 16) + mi * 16 + (lane & 15);
                int col = ks * 16 + (lane >> 4) * 8;
                uint32_t addr = smem_u32(&sa[row * HPAD + col]);
                asm volatile("ldmatrix.sync.aligned.m8n8.x4.shared.b16 {%0,%1,%2,%3}, [%4];\n"
                             : "=r"(a[mi][0]), "=r"(a[mi][1]), "=r"(a[mi][2]), "=r"(a[mi][3])
                             : "r"(addr));
            }
#pragma unroll
            for (int j = 0; j < NI / 2; j++) {
                int n   = wc * 32 + j * 16 + (lane & 7) + ((lane >> 4) << 3);
                int col = ks * 16 + ((lane >> 3) & 1) * 8;
                uint32_t addr = smem_u32(&sb[n * HPAD + col]);
                uint32_t r0, r1, r2, r3;
                asm volatile("ldmatrix.sync.aligned.m8n8.x4.shared.b16 {%0,%1,%2,%3}, [%4];\n"
                             : "=r"(r0), "=r"(r1), "=r"(r2), "=r"(r3) : "r"(addr));
                b[2 * j][0] = r0; b[2 * j][1] = r1;
                b[2 * j + 1][0] = r2; b[2 * j + 1][1] = r3;
            }
#pragma unroll
            for (int mi = 0; mi < MI; mi++)
#pragma unroll
                for (int ni = 0; ni < NI; ni++)
                    asm volatile(
                        "mma.sync.aligned.m16n8k16.row.col.f32.f16.f16.f32 "
                        "{%0,%1,%2,%3}, {%4,%5,%6,%7}, {%8,%9}, {%0,%1,%2,%3};\n"
                        : "+f"(acc[mi][ni][0]), "+f"(acc[mi][ni][1]),
                          "+f"(acc[mi][ni][2]), "+f"(acc[mi][ni][3])
                        : "r"(a[mi][0]), "r"(a[mi][1]), "r"(a[mi][2]), "r"(a[mi][3]),
                          "r"(b[ni][0]), "r"(b[ni][1]));
        }
    }
    __syncthreads();

    // epilogue
#pragma unroll
    for (int mi = 0; mi < MI; mi++) {
        int row = m0 + wr * (MI * 16) + mi * 16 + (lane >> 2);
#pragma unroll
        for (int ni = 0; ni < NI; ni++) {
            int col = n0 + wc * 32 + ni * 8 + (lane & 3) * 2;
            float2 lo = make_float2(acc[mi][ni][0] * alpha, acc[mi][ni][1] * alpha);
            float2 hi = make_float2(acc[mi][ni][2] * alpha, acc[mi][ni][3] * alpha);
            if (BIASM == 1) {
                float b0 = bias[col], b1 = bias[col + 1];
                lo.x += b0; lo.y += b1; hi.x += b0; hi.y += b1;
            }
            if (BIASM == 2) {
                float br = bias[row], br8 = bias[row + 8];
                lo.x += br; lo.y += br; hi.x += br8; hi.y += br8;
            }
            if (CADDM == 1) {
                const float* ca = CaddF + z * sAdd;
                float2 c0 = *(const float2*)&ca[(size_t)row * ldadd + col];
                float2 c1 = *(const float2*)&ca[(size_t)(row + 8) * ldadd + col];
                lo.x += c0.x; lo.y += c0.y;
                hi.x += c1.x; hi.y += c1.y;
            }
            if (CADDM == 2) {
                const __half* ca = CaddH + z * sAdd;
                float2 c0 = __half22float2(*(const __half2*)&ca[(size_t)row * ldadd + col]);
                float2 c1 = __half22float2(*(const __half2*)&ca[(size_t)(row + 8) * ldadd + col]);
                lo.x += c0.x; lo.y += c0.y;
                hi.x += c1.x; hi.y += c1.y;
            }
            if (RELU) {
                lo.x = fmaxf(lo.x, 0.f); lo.y = fmaxf(lo.y, 0.f);
                hi.x = fmaxf(hi.x, 0.f); hi.y = fmaxf(hi.y, 0.f);
            }
            if (OUTF16) {
                __half* co = Ch + z * sC;
                *(__half2*)&co[(size_t)row * ldc + col]       = __floats2half2_rn(lo.x, lo.y);
                *(__half2*)&co[(size_t)(row + 8) * ldc + col] = __floats2half2_rn(hi.x, hi.y);
            } else {
                float* co = C + z * sC;
                *(float2*)&co[(size_t)row * ldc + col]       = lo;
                *(float2*)&co[(size_t)(row + 8) * ldc + col] = hi;
            }
        }
    }
}

template<int BN, bool RELU, int CADDM, bool OUTF16, int BIASM>
static inline void hgemm(const __half* A, int lda, long sA,
                         const __half* B, int ldb, long sB,
                         float* C, __half* Ch, int ldc, long sC,
                         const float* CaddF, const __half* CaddH, int ldadd, long sAdd,
                         const float* bias, float alpha,
                         int Md, int Nd, int Kd, int batch)
{
    constexpr int SMEM = 3 * (128 + BN) * HPAD * 2;
    cudaFuncSetAttribute(hgemm_k<BN, RELU, CADDM, OUTF16, BIASM>,
                         cudaFuncAttributeMaxDynamicSharedMemorySize, SMEM);
    dim3 grid(Nd / BN, Md / 128, batch);
    hgemm_k<BN, RELU, CADDM, OUTF16, BIASM><<<grid, 256, SMEM>>>(
        A, lda, sA, B, ldb, sB, C, Ch, ldc, sC, CaddF, CaddH, ldadd, sAdd,
        bias, alpha, Md, Nd, Kd);
}

// ---------------- conversions ----------------
__global__ void __launch_bounds__(256)
conv_k(const float4* __restrict__ in, __half2* __restrict__ out, int n4)
{
    int i = blockIdx.x * 256 + threadIdx.x;
    if (i < n4) {
        float4 v = in[i];
        out[2 * i]     = __floats2half2_rn(v.x, v.y);
        out[2 * i + 1] = __floats2half2_rn(v.z, v.w);
    }
}

// out[C][R] (f16) = transpose of in[R][C] (f32). R,C multiples of 32.
__global__ void __launch_bounds__(256)
tconv_f2h_k(const float* __restrict__ in, __half* __restrict__ out, int R, int C)
{
    __shared__ float t[32][33];
    int c0 = blockIdx.x * 32, r0 = blockIdx.y * 32;
    int x = threadIdx.x & 31, y = threadIdx.x >> 5;
#pragma unroll
    for (int j = 0; j < 32; j += 8)
        t[y + j][x] = in[(size_t)(r0 + y + j) * C + c0 + x];
    __syncthreads();
#pragma unroll
    for (int j = 0; j < 32; j += 8)
        out[(size_t)(c0 + y + j) * R + r0 + x] = __float2half(t[x][y + j]);
}

// out[C][R] (f16) = transpose of in[R][C] (f16). R,C multiples of 32.
__global__ void __launch_bounds__(256)
tconv_h2h_k(const __half* __restrict__ in, __half* __restrict__ out, int R, int C)
{
    __shared__ __half t[32][34];
    int c0 = blockIdx.x * 32, r0 = blockIdx.y * 32;
    int x = threadIdx.x & 31, y = threadIdx.x >> 5;
#pragma unroll
    for (int j = 0; j < 32; j += 8)
        t[y + j][x] = in[(size_t)(r0 + y + j) * C + c0 + x];
    __syncthreads();
#pragma unroll
    for (int j = 0; j < 32; j += 8)
        out[(size_t)(c0 + y + j) * R + r0 + x] = t[x][y + j];
}

// ---------------- reductions ----------------
__device__ __forceinline__ float warpRedMax(float v) {
#pragma unroll
    for (int o = 16; o > 0; o >>= 1) v = fmaxf(v, __shfl_xor_sync(0xffffffffu, v, o));
    return v;
}
__device__ __forceinline__ float warpRedSum(float v) {
#pragma unroll
    for (int o = 16; o > 0; o >>= 1) v += __shfl_xor_sync(0xffffffffu, v, o);
    return v;
}
__device__ __forceinline__ float blockMax256(float v, float* red) {
    int lane = threadIdx.x & 31, w = threadIdx.x >> 5;
    v = warpRedMax(v);
    if (lane == 0) red[w] = v;
    __syncthreads();
    float r = red[0];
#pragma unroll
    for (int i = 1; i < 8; i++) r = fmaxf(r, red[i]);
    __syncthreads();
    return r;
}
__device__ __forceinline__ float blockSum256(float v, float* red) {
    int lane = threadIdx.x & 31, w = threadIdx.x >> 5;
    v = warpRedSum(v);
    if (lane == 0) red[w] = v;
    __syncthreads();
    float r = 0.f;
#pragma unroll
    for (int i = 0; i < 8; i++) r += red[i];
    __syncthreads();
    return r;
}

// ---------------- masked softmax, in place on fp16 scores ----------------
__global__ void __launch_bounds__(256)
softmax16_k(__half* __restrict__ S, const int* __restrict__ mask)
{
    __shared__ float red[8];
    const int l = blockIdx.x, h = blockIdx.y;
    __half* row = S + (size_t)l * HK + (size_t)h * M_DIM;
    const int* mrow = mask + (size_t)l * M_DIM;
    const int t = threadIdx.x;

    float v[4];
    float mx = -3.4e38f;
#pragma unroll
    for (int i = 0; i < 4; i++) {
        int m = t + i * 256;
        float s = __half2float(row[m]);
        s = (mrow[m] != 0) ? s : -1e9f;
        v[i] = s;
        mx = fmaxf(mx, s);
    }
    mx = blockMax256(mx, red);
    float sum = 0.f;
#pragma unroll
    for (int i = 0; i < 4; i++) {
        float e = __expf(v[i] - mx);
        v[i] = e;
        sum += e;
    }
    sum = blockSum256(sum, red);
    float inv = __frcp_rn(sum);
#pragma unroll
    for (int i = 0; i < 4; i++) row[t + i * 256] = __float2half(v[i] * inv);
}

// ---------------- layernorm ----------------
__global__ void __launch_bounds__(256)
ln_k(const float* __restrict__ x, const float* __restrict__ g, const float* __restrict__ be,
     float* __restrict__ out)
{
    __shared__ float red[8];
    const int r = blockIdx.x, t = threadIdx.x;
    float v = x[r * 256 + t];
    float mean = blockSum256(v, red) * (1.f / 256.f);
    float d = v - mean;
    float var = blockSum256(d * d, red) * (1.f / 256.f);
    out[r * 256 + t] = d * rsqrtf(var + EPS_LN) * g[t] + be[t];
}

// ---------------- launch ----------------
static inline void* symraw(const void* s) {
    void* p = nullptr;
    cudaGetSymbolAddress(&p, s);
    return p;
}

extern "C" void kernel_launch(void* const* d_in, const int* in_sizes, int n_in,
                              void* d_out, int out_size)
{
    (void)in_sizes; (void)n_in; (void)out_size;
    const float* Le    = (const float*)d_in[0];
    const float* Me    = (const float*)d_in[1];
    const float* Pe    = (const float*)d_in[2];
    const int*   maskL = (const int*)  d_in[3];
    const int*   maskP = (const int*)  d_in[4];
    const float *Wl  = (const float*)d_in[5],  *bl  = (const float*)d_in[6];
    const float *Wm  = (const float*)d_in[7],  *bm  = (const float*)d_in[8];
    const float *Wp  = (const float*)d_in[9],  *bp  = (const float*)d_in[10];
    const float *Wql = (const float*)d_in[11], *bql = (const float*)d_in[12];
    const float *Wkl = (const float*)d_in[13], *bkl = (const float*)d_in[14];
    const float *Wvl = (const float*)d_in[15], *bvl = (const float*)d_in[16];
    const float *Wqp = (const float*)d_in[17], *bqp = (const float*)d_in[18];
    const float *Wkp = (const float*)d_in[19], *bkp = (const float*)d_in[20];
    const float *Wvp = (const float*)d_in[21], *bvp = (const float*)d_in[22];
    const float *Wml = (const float*)d_in[23], *bml = (const float*)d_in[24];
    const float *Wmp = (const float*)d_in[25], *bmp = (const float*)d_in[26];
    const float *g1  = (const float*)d_in[27], *be1 = (const float*)d_in[28];
    const float *g2  = (const float*)d_in[29], *be2 = (const float*)d_in[30];

    float* preL = (float*)symraw(g_preL);
    float* preP = (float*)symraw(g_preP);

    __half* hLe  = (__half*)symraw(g_hLe);
    __half* hMe  = (__half*)symraw(g_hMe);
    __half* hPe  = (__half*)symraw(g_hPe);
    __half* hWlT = (__half*)symraw(g_hWlT);
    __half* hWmT = (__half*)symraw(g_hWmT);
    __half* hWpT = (__half*)symraw(g_hWpT);
    __half* hWqlT= (__half*)symraw(g_hWqlT);
    __half* hWklT= (__half*)symraw(g_hWklT);
    __half* hWvlT= (__half*)symraw(g_hWvlT);
    __half* hWqpT= (__half*)symraw(g_hWqpT);
    __half* hWkpT= (__half*)symraw(g_hWkpT);
    __half* hWvpT= (__half*)symraw(g_hWvpT);
    __half* hWmlT= (__half*)symraw(g_hWmlT);
    __half* hWmpT= (__half*)symraw(g_hWmpT);

    __half* hlt  = (__half*)symraw(g_hlt);
    __half* hmt  = (__half*)symraw(g_hmt);
    __half* hpt  = (__half*)symraw(g_hpt);
    __half* hQl  = (__half*)symraw(g_hQl);
    __half* hKl  = (__half*)symraw(g_hKl);
    __half* hQp  = (__half*)symraw(g_hQp);
    __half* hKp  = (__half*)symraw(g_hKp);
    __half* hVlT = (__half*)symraw(g_hVlT);
    __half* hVpT = (__half*)symraw(g_hVpT);
    __half* hawl = (__half*)symraw(g_hawl);
    __half* hawlT= (__half*)symraw(g_hawlT);
    __half* hawp = (__half*)symraw(g_hawp);
    __half* hawpT= (__half*)symraw(g_hawpT);
    __half* hctxl= (__half*)symraw(g_hctxl);
    __half* hctxp= (__half*)symraw(g_hctxp);
    __half* hctxlT=(__half*)symraw(g_hctxlT);
    __half* hctxpT=(__half*)symraw(g_hctxpT);
    __half* hTpT = (__half*)symraw(g_hTpT);
    __half* hTlT = (__half*)symraw(g_hTlT);
    __half* hfinl= (__half*)symraw(g_hfinl);
    __half* hfinp= (__half*)symraw(g_hfinp);

    const float scale = 0.125f;   // 1/sqrt(DH)
    const float invH  = 0.125f;   // 1/H

    // 0) inputs + weights -> fp16 (weights transposed to [N][K])
    conv_k<<<(L_DIM * HID / 4 + 255) / 256, 256>>>((const float4*)Le, (__half2*)hLe, L_DIM * HID / 4);
    conv_k<<<(M_DIM * HID / 4 + 255) / 256, 256>>>((const float4*)Me, (__half2*)hMe, M_DIM * HID / 4);
    conv_k<<<(P_DIM * HID / 4 + 255) / 256, 256>>>((const float4*)Pe, (__half2*)hPe, P_DIM * HID / 4);
    {
        dim3 gw(HID / 32, HID / 32);
        tconv_f2h_k<<<gw, 256>>>(Wl,  hWlT,  HID, HID);
        tconv_f2h_k<<<gw, 256>>>(Wm,  hWmT,  HID, HID);
        tconv_f2h_k<<<gw, 256>>>(Wp,  hWpT,  HID, HID);
        tconv_f2h_k<<<gw, 256>>>(Wql, hWqlT, HID, HID);
        tconv_f2h_k<<<gw, 256>>>(Wkl, hWklT, HID, HID);
        tconv_f2h_k<<<gw, 256>>>(Wvl, hWvlT, HID, HID);
        tconv_f2h_k<<<gw, 256>>>(Wqp, hWqpT, HID, HID);
        tconv_f2h_k<<<gw, 256>>>(Wkp, hWkpT, HID, HID);
        tconv_f2h_k<<<gw, 256>>>(Wvp, hWvpT, HID, HID);
        dim3 gw2(DHALF / 32, 2 * HID / 32);
        tconv_f2h_k<<<gw2, 256>>>(Wml, hWmlT, 2 * HID, DHALF);
        tconv_f2h_k<<<gw2, 256>>>(Wmp, hWmpT, 2 * HID, DHALF);
    }

    // 1) input projections (fp16 out)
    hgemm<128,false,0,true,1>(hLe, HID, 0, hWlT, HID, 0, nullptr, hlt, HID, 0,
                              nullptr, nullptr, 0, 0, bl, 1.f, L_DIM, HID, HID, 1);
    hgemm<128,false,0,true,1>(hMe, HID, 0, hWmT, HID, 0, nullptr, hmt, HID, 0,
                              nullptr, nullptr, 0, 0, bm, 1.f, M_DIM, HID, HID, 1);
    hgemm<128,false,0,true,1>(hPe, HID, 0, hWpT, HID, 0, nullptr, hpt, HID, 0,
                              nullptr, nullptr, 0, 0, bp, 1.f, P_DIM, HID, HID, 1);

    // 2) Q/K projections (fp16), V directly transposed (A = W^T, B = x, row bias)
    hgemm<128,false,0,true,1>(hlt, HID, 0, hWqlT, HID, 0, nullptr, hQl, HID, 0,
                              nullptr, nullptr, 0, 0, bql, 1.f, L_DIM, HID, HID, 1);
    hgemm<128,false,0,true,1>(hmt, HID, 0, hWklT, HID, 0, nullptr, hKl, HID, 0,
                              nullptr, nullptr, 0, 0, bkl, 1.f, M_DIM, HID, HID, 1);
    hgemm<128,false,0,true,1>(hpt, HID, 0, hWqpT, HID, 0, nullptr, hQp, HID, 0,
                              nullptr, nullptr, 0, 0, bqp, 1.f, P_DIM, HID, HID, 1);
    hgemm<128,false,0,true,1>(hmt, HID, 0, hWkpT, HID, 0, nullptr, hKp, HID, 0,
                              nullptr, nullptr, 0, 0, bkp, 1.f, M_DIM, HID, HID, 1);
    hgemm<128,false,0,true,2>(hWvlT, HID, 0, hmt, HID, 0, nullptr, hVlT, M_DIM, 0,
                              nullptr, nullptr, 0, 0, bvl, 1.f, HID, M_DIM, HID, 1);
    hgemm<128,false,0,true,2>(hWvpT, HID, 0, hmt, HID, 0, nullptr, hVpT, M_DIM, 0,
                              nullptr, nullptr, 0, 0, bvp, 1.f, HID, M_DIM, HID, 1);

    // 3) attention scores (batched over heads) -> fp16 score buffer
    hgemm<128,false,0,true,0>(hQl, HID, DH, hKl, HID, DH, nullptr, hawl, HK, M_DIM,
                              nullptr, nullptr, 0, 0, nullptr, scale, L_DIM, M_DIM, DH, NH);
    hgemm<128,false,0,true,0>(hQp, HID, DH, hKp, HID, DH, nullptr, hawp, HK, M_DIM,
                              nullptr, nullptr, 0, 0, nullptr, scale, P_DIM, M_DIM, DH, NH);

    // 4) masked softmax, in place
    softmax16_k<<<dim3(L_DIM, NH), 256>>>(hawl, maskL);
    softmax16_k<<<dim3(P_DIM, NH), 256>>>(hawp, maskP);

    // 5) context (BN=64, relu) -> fp16 ctx
    hgemm<64,true,0,true,0>(hawl, HK, M_DIM, hVlT, M_DIM, (long)DH * M_DIM,
                            nullptr, hctxl, HID, DH, nullptr, nullptr, 0, 0,
                            nullptr, 1.f, L_DIM, DH, M_DIM, NH);
    hgemm<64,true,0,true,0>(hawp, HK, M_DIM, hVpT, M_DIM, (long)DH * M_DIM,
                            nullptr, hctxp, HID, DH, nullptr, nullptr, 0, 0,
                            nullptr, 1.f, P_DIM, DH, M_DIM, NH);

    // 6) transposed copies for the mutual chain
    tconv_h2h_k<<<dim3(HK / 32, L_DIM / 32), 256>>>(hawl, hawlT, L_DIM, HK);
    tconv_h2h_k<<<dim3(HK / 32, P_DIM / 32), 256>>>(hawp, hawpT, P_DIM, HK);
    tconv_h2h_k<<<dim3(HID / 32, L_DIM / 32), 256>>>(hctxl, hctxlT, L_DIM, HID);
    tconv_h2h_k<<<dim3(HID / 32, P_DIM / 32), 256>>>(hctxp, hctxpT, P_DIM, HID);

    // 7) reassociated mutual:
    //    hTpT[HID,HK] = ctxp^T @ awp ;  finl = ctxl + (1/H) * awl @ hTpT^T
    //    hTlT[HID,HK] = ctxl^T @ awl ;  finp = ctxp + (1/H) * awp @ hTlT^T
    hgemm<128,false,0,true,0>(hctxpT, P_DIM, 0, hawpT, P_DIM, 0, nullptr, hTpT, HK, 0,
                              nullptr, nullptr, 0, 0, nullptr, 1.f, HID, HK, P_DIM, 1);
    hgemm<128,false,2,true,0>(hawl, HK, 0, hTpT, HK, 0, nullptr, hfinl, HID, 0,
                              nullptr, hctxl, HID, 0, nullptr, invH, L_DIM, HID, HK, 1);
    hgemm<128,false,0,true,0>(hctxlT, L_DIM, 0, hawlT, L_DIM, 0, nullptr, hTlT, HK, 0,
                              nullptr, nullptr, 0, 0, nullptr, 1.f, HID, HK, L_DIM, 1);
    hgemm<128,false,2,true,0>(hawp, HK, 0, hTlT, HK, 0, nullptr, hfinp, HID, 0,
                              nullptr, hctxp, HID, 0, nullptr, invH, P_DIM, HID, HK, 1);

    // 8) final linears (split-weight accumulate, f32 out for LN)
    hgemm<128,false,0,false,1>(hlt, HID, 0, hWmlT, 2 * HID, 0, preL, nullptr, DHALF, 0,
                               nullptr, nullptr, 0, 0, bml, 1.f, L_DIM, DHALF, HID, 1);
    hgemm<128,false,1,false,0>(hfinl, HID, 0, hWmlT + HID, 2 * HID, 0, preL, nullptr, DHALF, 0,
                               preL, nullptr, DHALF, 0, nullptr, 1.f, L_DIM, DHALF, HID, 1);
    hgemm<128,false,0,false,1>(hfinp, HID, 0, hWmpT, 2 * HID, 0, preP, nullptr, DHALF, 0,
                               nullptr, nullptr, 0, 0, bmp, 1.f, P_DIM, DHALF, HID, 1);
    hgemm<128,false,1,false,0>(hpt, HID, 0, hWmpT + HID, 2 * HID, 0, preP, nullptr, DHALF, 0,
                               preP, nullptr, DHALF, 0, nullptr, 1.f, P_DIM, DHALF, HID, 1);

    // 9) layernorms -> output
    float* out = (float*)d_out;
    ln_k<<<L_DIM, 256>>>(preL, g1, be1, out);
    ln_k<<<P_DIM, 256>>>(preP, g2, be2, out + (size_t)L_DIM * DHALF);
}